// round 2
// baseline (speedup 1.0000x reference)
#include <cuda_runtime.h>
#include <math.h>

#define SS 512
#define II 384
#define CM 64
#define CZ 128
#define HH 8
#define CC 32
#define HC 256
#define EPS 1e-5f

// Scratch (static device allocations; allowed)
__device__ float g_N[SS * II * CM];          // msa_n                [s*384+i][64]
__device__ float g_V[(size_t)HH * II * SS * CC];  // V                [h][j][s*32+c]
__device__ float g_W[II * HH * II];          // bias -> softmax w    [i][h][j]
__device__ float g_O[(size_t)SS * II * HC];  // einsum result        [s*384+i][h*32+c]

// ---------------------------------------------------------------------------
// K_A: LN(msa) + V = msa_n @ W_v. 16 rows per block, 256 threads.
// ---------------------------------------------------------------------------
__global__ void kA(const float* __restrict__ msa, const float* __restrict__ gg,
                   const float* __restrict__ bb, const float* __restrict__ Wv) {
    extern __shared__ float sm[];
    float* Wv_s = sm;            // 64*256
    float* xn   = sm + CM * HC;  // 16*64
    int t = threadIdx.x;
    for (int idx = t; idx < CM * HC; idx += 256) Wv_s[idx] = Wv[idx];

    int row0 = blockIdx.x * 16;
    int r = t >> 4, l = t & 15;
    const float* x = msa + (size_t)(row0 + r) * CM + l * 4;
    float v0 = x[0], v1 = x[1], v2 = x[2], v3 = x[3];
    float sum = v0 + v1 + v2 + v3;
    float sq  = v0*v0 + v1*v1 + v2*v2 + v3*v3;
#pragma unroll
    for (int o = 8; o > 0; o >>= 1) {
        sum += __shfl_xor_sync(0xffffffffu, sum, o);
        sq  += __shfl_xor_sync(0xffffffffu, sq,  o);
    }
    float mean = sum * (1.0f / CM);
    float var  = sq * (1.0f / CM) - mean * mean;
    float rstd = rsqrtf(var + EPS);
    int k0 = l * 4;
    float n0 = (v0 - mean) * rstd * gg[k0+0] + bb[k0+0];
    float n1 = (v1 - mean) * rstd * gg[k0+1] + bb[k0+1];
    float n2 = (v2 - mean) * rstd * gg[k0+2] + bb[k0+2];
    float n3 = (v3 - mean) * rstd * gg[k0+3] + bb[k0+3];
    xn[r * CM + k0 + 0] = n0;
    xn[r * CM + k0 + 1] = n1;
    xn[r * CM + k0 + 2] = n2;
    xn[r * CM + k0 + 3] = n3;
    float* Ng = g_N + (size_t)(row0 + r) * CM + k0;
    Ng[0] = n0; Ng[1] = n1; Ng[2] = n2; Ng[3] = n3;
    __syncthreads();

    float acc[16];
#pragma unroll
    for (int rr = 0; rr < 16; rr++) acc[rr] = 0.f;
    for (int k = 0; k < CM; k += 4) {
        float w0 = Wv_s[(k+0) * HC + t];
        float w1 = Wv_s[(k+1) * HC + t];
        float w2 = Wv_s[(k+2) * HC + t];
        float w3 = Wv_s[(k+3) * HC + t];
#pragma unroll
        for (int rr = 0; rr < 16; rr++) {
            float4 xv = *(const float4*)&xn[rr * CM + k];
            acc[rr] += xv.x * w0 + xv.y * w1 + xv.z * w2 + xv.w * w3;
        }
    }
    int h = t >> 5, c = t & 31;
#pragma unroll
    for (int rr = 0; rr < 16; rr++) {
        int row = row0 + rr;
        int s = row / II, i = row % II;
        g_V[(((size_t)h * II + i) * SS + s) * CC + c] = acc[rr];
    }
}

// ---------------------------------------------------------------------------
// K_B: LN(pair) @ W_bias -> g_W[i][h][j]. One warp per (i,j) row.
// ---------------------------------------------------------------------------
__global__ void kB(const float* __restrict__ pair, const float* __restrict__ gg,
                   const float* __restrict__ bb, const float* __restrict__ Wb) {
    int warp = threadIdx.x >> 5, lane = threadIdx.x & 31;
    int row = blockIdx.x * 8 + warp;  // i*384 + j
    const float4* x4 = (const float4*)(pair + (size_t)row * CZ);
    float4 v = x4[lane];
    float sum = v.x + v.y + v.z + v.w;
    float sq  = v.x*v.x + v.y*v.y + v.z*v.z + v.w*v.w;
#pragma unroll
    for (int o = 16; o > 0; o >>= 1) {
        sum += __shfl_xor_sync(0xffffffffu, sum, o);
        sq  += __shfl_xor_sync(0xffffffffu, sq,  o);
    }
    float mean = sum * (1.0f / CZ);
    float var  = sq * (1.0f / CZ) - mean * mean;
    float rstd = rsqrtf(var + EPS);
    int k0 = lane * 4;
    float n0 = (v.x - mean) * rstd * gg[k0+0] + bb[k0+0];
    float n1 = (v.y - mean) * rstd * gg[k0+1] + bb[k0+1];
    float n2 = (v.z - mean) * rstd * gg[k0+2] + bb[k0+2];
    float n3 = (v.w - mean) * rstd * gg[k0+3] + bb[k0+3];
    float ph[HH];
#pragma unroll
    for (int h = 0; h < HH; h++) {
        ph[h] = n0 * Wb[(k0+0)*HH + h] + n1 * Wb[(k0+1)*HH + h]
              + n2 * Wb[(k0+2)*HH + h] + n3 * Wb[(k0+3)*HH + h];
    }
#pragma unroll
    for (int h = 0; h < HH; h++) {
#pragma unroll
        for (int o = 16; o > 0; o >>= 1)
            ph[h] += __shfl_xor_sync(0xffffffffu, ph[h], o);
    }
    if (lane == 0) {
        int i = row / II, j = row % II;
#pragma unroll
        for (int h = 0; h < HH; h++)
            g_W[((size_t)i * HH + h) * II + j] = ph[h];
    }
}

// ---------------------------------------------------------------------------
// K_C: in-place softmax over j for each (i,h). 128 threads, 3 elems each.
// ---------------------------------------------------------------------------
__global__ void kC() {
    int row = blockIdx.x;  // i*8 + h
    float* p = g_W + (size_t)row * II;
    int t = threadIdx.x;
    __shared__ float red[128];
    float x0 = p[t], x1 = p[t + 128], x2 = p[t + 256];
    float m = fmaxf(x0, fmaxf(x1, x2));
    red[t] = m;
    __syncthreads();
    for (int o = 64; o > 0; o >>= 1) {
        if (t < o) red[t] = fmaxf(red[t], red[t + o]);
        __syncthreads();
    }
    m = red[0];
    __syncthreads();
    float e0 = __expf(x0 - m), e1 = __expf(x1 - m), e2 = __expf(x2 - m);
    red[t] = e0 + e1 + e2;
    __syncthreads();
    for (int o = 64; o > 0; o >>= 1) {
        if (t < o) red[t] += red[t + o];
        __syncthreads();
    }
    float inv = 1.0f / red[0];
    p[t] = e0 * inv; p[t + 128] = e1 * inv; p[t + 256] = e2 * inv;
}

// ---------------------------------------------------------------------------
// K_D: per-h GEMM  C_h[i][n] = sum_j w[i][h][j] * V[h][j][n],  n = s*32+c.
// BM=BN=64, BK=16, 256 threads, 4x4 per thread.
// ---------------------------------------------------------------------------
__global__ void kD() {
    const int h  = blockIdx.z;
    const int i0 = blockIdx.y * 64;
    const int n0 = blockIdx.x * 64;
    __shared__ float As[16][64];
    __shared__ float Bs[16][64];
    int tid = threadIdx.x;
    int tx = tid & 15, ty = tid >> 4;
    int arow = tid >> 2, acol0 = (tid & 3) * 4;
    int brow = tid >> 4, bcol0 = (tid & 15) * 4;

    float acc[4][4];
#pragma unroll
    for (int r = 0; r < 4; r++)
#pragma unroll
        for (int c = 0; c < 4; c++) acc[r][c] = 0.f;

    for (int k0 = 0; k0 < II; k0 += 16) {
        float4 a = *(const float4*)&g_W[((size_t)(i0 + arow) * HH + h) * II + k0 + acol0];
        As[acol0 + 0][arow] = a.x;
        As[acol0 + 1][arow] = a.y;
        As[acol0 + 2][arow] = a.z;
        As[acol0 + 3][arow] = a.w;
        *(float4*)&Bs[brow][bcol0] =
            *(const float4*)&g_V[((size_t)h * II + (k0 + brow)) * (SS * CC) + n0 + bcol0];
        __syncthreads();
#pragma unroll
        for (int k = 0; k < 16; k++) {
            float4 av = *(const float4*)&As[k][ty * 4];
            float4 bv = *(const float4*)&Bs[k][tx * 4];
            acc[0][0] += av.x * bv.x; acc[0][1] += av.x * bv.y;
            acc[0][2] += av.x * bv.z; acc[0][3] += av.x * bv.w;
            acc[1][0] += av.y * bv.x; acc[1][1] += av.y * bv.y;
            acc[1][2] += av.y * bv.z; acc[1][3] += av.y * bv.w;
            acc[2][0] += av.z * bv.x; acc[2][1] += av.z * bv.y;
            acc[2][2] += av.z * bv.z; acc[2][3] += av.z * bv.w;
            acc[3][0] += av.w * bv.x; acc[3][1] += av.w * bv.y;
            acc[3][2] += av.w * bv.z; acc[3][3] += av.w * bv.w;
        }
        __syncthreads();
    }
#pragma unroll
    for (int r = 0; r < 4; r++) {
        int i = i0 + ty * 4 + r;
        int n = n0 + tx * 4;
        int s = n >> 5, c = n & 31;
        float4 o = make_float4(acc[r][0], acc[r][1], acc[r][2], acc[r][3]);
        *(float4*)&g_O[((size_t)s * II + i) * HC + h * CC + c] = o;
    }
}

// ---------------------------------------------------------------------------
// K_E: gate = sigmoid(msa_n @ W_gate); out = (gate * weights) @ W_out.
// 16 rows per block, 256 threads.
// ---------------------------------------------------------------------------
__global__ void kE(const float* __restrict__ Wg, const float* __restrict__ Wo,
                   float* __restrict__ out) {
    extern __shared__ float sm[];
    float* Wg_s = sm;              // 16384
    float* Wo_s = sm + 16384;      // 16384
    float* xn   = sm + 32768;      // 1024
    float* os   = sm + 33792;      // 4096
    int t = threadIdx.x;
    for (int idx = t; idx < 16384; idx += 256) {
        Wg_s[idx] = Wg[idx];
        Wo_s[idx] = Wo[idx];
    }
    int row0 = blockIdx.x * 16;
    {
        float4 v = *(const float4*)&g_N[(size_t)row0 * CM + t * 4];
        *(float4*)&xn[t * 4] = v;
    }
    __syncthreads();

    float acc[16];
#pragma unroll
    for (int rr = 0; rr < 16; rr++) acc[rr] = 0.f;
    for (int k = 0; k < CM; k += 4) {
        float w0 = Wg_s[(k+0) * HC + t];
        float w1 = Wg_s[(k+1) * HC + t];
        float w2 = Wg_s[(k+2) * HC + t];
        float w3 = Wg_s[(k+3) * HC + t];
#pragma unroll
        for (int rr = 0; rr < 16; rr++) {
            float4 xv = *(const float4*)&xn[rr * CM + k];
            acc[rr] += xv.x * w0 + xv.y * w1 + xv.z * w2 + xv.w * w3;
        }
    }
    const float* Ob = g_O + (size_t)row0 * HC + t;
#pragma unroll
    for (int rr = 0; rr < 16; rr++) {
        float gate = 1.0f / (1.0f + __expf(-acc[rr]));
        os[rr * HC + t] = gate * Ob[(size_t)rr * HC];
    }
    __syncthreads();

    int n = t & 63, r0 = t >> 6;
    float a2[4] = {0.f, 0.f, 0.f, 0.f};
    for (int k = 0; k < HC; k += 4) {
        float w0 = Wo_s[(k+0) * CM + n];
        float w1 = Wo_s[(k+1) * CM + n];
        float w2 = Wo_s[(k+2) * CM + n];
        float w3 = Wo_s[(k+3) * CM + n];
#pragma unroll
        for (int q = 0; q < 4; q++) {
            float4 ov = *(const float4*)&os[(r0 + 4*q) * HC + k];
            a2[q] += ov.x * w0 + ov.y * w1 + ov.z * w2 + ov.w * w3;
        }
    }
#pragma unroll
    for (int q = 0; q < 4; q++)
        out[(size_t)(row0 + r0 + 4*q) * CM + n] = a2[q];
}

// ---------------------------------------------------------------------------
extern "C" void kernel_launch(void* const* d_in, const int* in_sizes, int n_in,
                              void* d_out, int out_size) {
    const float* msa  = (const float*)d_in[0];
    const float* pair = (const float*)d_in[1];
    const float* g1   = (const float*)d_in[2];
    const float* b1   = (const float*)d_in[3];
    const float* g2   = (const float*)d_in[4];
    const float* b2   = (const float*)d_in[5];
    const float* Wv   = (const float*)d_in[6];
    const float* Wb   = (const float*)d_in[7];
    const float* Wg   = (const float*)d_in[8];
    const float* Wo   = (const float*)d_in[9];
    float* out = (float*)d_out;

    static const size_t A_SMEM = (CM * HC + 16 * CM) * sizeof(float);          // 69632
    static const size_t E_SMEM = (16384 + 16384 + 1024 + 4096) * sizeof(float); // 151552
    cudaFuncSetAttribute(kA, cudaFuncAttributeMaxDynamicSharedMemorySize, (int)A_SMEM);
    cudaFuncSetAttribute(kE, cudaFuncAttributeMaxDynamicSharedMemorySize, (int)E_SMEM);

    kA<<<SS * II / 16, 256, A_SMEM>>>(msa, g1, b1, Wv);
    kB<<<II * II / 8, 256>>>(pair, g2, b2, Wb);
    kC<<<II * HH, 128>>>();
    kD<<<dim3((SS * CC) / 64, II / 64, HH), 256>>>();
    kE<<<SS * II / 16, 256, E_SMEM>>>(Wg, Wo, out);
}

// round 4
// speedup vs baseline: 1.4860x; 1.4860x over previous
#include <cuda_runtime.h>
#include <math.h>
#include <stdint.h>

#define SS 512
#define II 384
#define CM 64
#define CZ 128
#define HH 8
#define CC 32
#define HC 256
#define NN (SS*CC)      // 16384
#define EPS 1e-5f

// Scratch (static device allocations; allowed)
__device__ float g_N[SS * II * CM];            // msa_n            [s*384+i][64]
__device__ float g_V[(size_t)HH * NN * II];    // V (tf32-rounded) [h][n=s*32+c][j=i]
__device__ float g_W[II * HH * II];            // softmax weights  [i][h][j] (tf32-rounded)
__device__ float g_O[(size_t)HH * NN * II];    // einsum result    [h][n][i]

__device__ __forceinline__ float to_tf32(float x) {
    uint32_t u;
    asm("cvt.rna.tf32.f32 %0, %1;" : "=r"(u) : "f"(x));
    return __uint_as_float(u);
}

__device__ __forceinline__ void mma8(float* d, const uint32_t* a, uint32_t b0, uint32_t b1) {
    asm volatile(
        "mma.sync.aligned.m16n8k8.row.col.f32.tf32.tf32.f32 "
        "{%0,%1,%2,%3}, {%4,%5,%6,%7}, {%8,%9}, {%0,%1,%2,%3};"
        : "+f"(d[0]), "+f"(d[1]), "+f"(d[2]), "+f"(d[3])
        : "r"(a[0]), "r"(a[1]), "r"(a[2]), "r"(a[3]), "r"(b0), "r"(b1));
}

// ---------------------------------------------------------------------------
// K_A: LN(msa) + V = msa_n @ W_v. 16 rows per block, 256 threads.
// Writes g_N (fp32) and g_V in [h][n][j] layout, tf32-rounded.
// ---------------------------------------------------------------------------
__global__ void kA(const float* __restrict__ msa, const float* __restrict__ gg,
                   const float* __restrict__ bb, const float* __restrict__ Wv) {
    extern __shared__ float sm[];
    float* Wv_s = sm;            // 64*256
    float* xn   = sm + CM * HC;  // 16*64
    int t = threadIdx.x;
    for (int idx = t; idx < CM * HC; idx += 256) Wv_s[idx] = Wv[idx];

    int row0 = blockIdx.x * 16;
    int r = t >> 4, l = t & 15;
    const float* x = msa + (size_t)(row0 + r) * CM + l * 4;
    float v0 = x[0], v1 = x[1], v2 = x[2], v3 = x[3];
    float sum = v0 + v1 + v2 + v3;
    float sq  = v0*v0 + v1*v1 + v2*v2 + v3*v3;
#pragma unroll
    for (int o = 8; o > 0; o >>= 1) {
        sum += __shfl_xor_sync(0xffffffffu, sum, o);
        sq  += __shfl_xor_sync(0xffffffffu, sq,  o);
    }
    float mean = sum * (1.0f / CM);
    float var  = sq * (1.0f / CM) - mean * mean;
    float rstd = rsqrtf(var + EPS);
    int k0 = l * 4;
    float n0 = (v0 - mean) * rstd * gg[k0+0] + bb[k0+0];
    float n1 = (v1 - mean) * rstd * gg[k0+1] + bb[k0+1];
    float n2 = (v2 - mean) * rstd * gg[k0+2] + bb[k0+2];
    float n3 = (v3 - mean) * rstd * gg[k0+3] + bb[k0+3];
    xn[r * CM + k0 + 0] = n0;
    xn[r * CM + k0 + 1] = n1;
    xn[r * CM + k0 + 2] = n2;
    xn[r * CM + k0 + 3] = n3;
    float* Ng = g_N + (size_t)(row0 + r) * CM + k0;
    Ng[0] = n0; Ng[1] = n1; Ng[2] = n2; Ng[3] = n3;
    __syncthreads();

    float acc[16];
#pragma unroll
    for (int rr = 0; rr < 16; rr++) acc[rr] = 0.f;
    for (int k = 0; k < CM; k += 4) {
        float w0 = Wv_s[(k+0) * HC + t];
        float w1 = Wv_s[(k+1) * HC + t];
        float w2 = Wv_s[(k+2) * HC + t];
        float w3 = Wv_s[(k+3) * HC + t];
#pragma unroll
        for (int rr = 0; rr < 16; rr++) {
            float4 xv = *(const float4*)&xn[rr * CM + k];
            acc[rr] += xv.x * w0 + xv.y * w1 + xv.z * w2 + xv.w * w3;
        }
    }
    // write V in [h][n = s*32+c][j = i] layout, tf32-rounded
    int h = t >> 5, c = t & 31;
    int s  = row0 / II;
    int ib = row0 % II;   // 16 consecutive i values
    float* Vp = g_V + ((size_t)h * NN + s * CC + c) * II + ib;
#pragma unroll
    for (int q = 0; q < 4; q++) {
        float4 o = make_float4(to_tf32(acc[4*q+0]), to_tf32(acc[4*q+1]),
                               to_tf32(acc[4*q+2]), to_tf32(acc[4*q+3]));
        *(float4*)(Vp + 4*q) = o;
    }
}

// ---------------------------------------------------------------------------
// K_B: LN(pair) @ W_bias -> g_W[i][h][j]. One warp per (i,j) row.
// ---------------------------------------------------------------------------
__global__ void kB(const float* __restrict__ pair, const float* __restrict__ gg,
                   const float* __restrict__ bb, const float* __restrict__ Wb) {
    int warp = threadIdx.x >> 5, lane = threadIdx.x & 31;
    int row = blockIdx.x * 8 + warp;  // i*384 + j
    const float4* x4 = (const float4*)(pair + (size_t)row * CZ);
    float4 v = x4[lane];
    float sum = v.x + v.y + v.z + v.w;
    float sq  = v.x*v.x + v.y*v.y + v.z*v.z + v.w*v.w;
#pragma unroll
    for (int o = 16; o > 0; o >>= 1) {
        sum += __shfl_xor_sync(0xffffffffu, sum, o);
        sq  += __shfl_xor_sync(0xffffffffu, sq,  o);
    }
    float mean = sum * (1.0f / CZ);
    float var  = sq * (1.0f / CZ) - mean * mean;
    float rstd = rsqrtf(var + EPS);
    int k0 = lane * 4;
    float n0 = (v.x - mean) * rstd * gg[k0+0] + bb[k0+0];
    float n1 = (v.y - mean) * rstd * gg[k0+1] + bb[k0+1];
    float n2 = (v.z - mean) * rstd * gg[k0+2] + bb[k0+2];
    float n3 = (v.w - mean) * rstd * gg[k0+3] + bb[k0+3];
    float ph[HH];
#pragma unroll
    for (int h = 0; h < HH; h++) {
        ph[h] = n0 * Wb[(k0+0)*HH + h] + n1 * Wb[(k0+1)*HH + h]
              + n2 * Wb[(k0+2)*HH + h] + n3 * Wb[(k0+3)*HH + h];
    }
#pragma unroll
    for (int h = 0; h < HH; h++) {
#pragma unroll
        for (int o = 16; o > 0; o >>= 1)
            ph[h] += __shfl_xor_sync(0xffffffffu, ph[h], o);
    }
    if (lane == 0) {
        int i = row / II, j = row % II;
#pragma unroll
        for (int h = 0; h < HH; h++)
            g_W[((size_t)i * HH + h) * II + j] = ph[h];
    }
}

// ---------------------------------------------------------------------------
// K_C: in-place softmax over j for each (i,h); output tf32-rounded.
// ---------------------------------------------------------------------------
__global__ void kC() {
    int row = blockIdx.x;  // i*8 + h
    float* p = g_W + (size_t)row * II;
    int t = threadIdx.x;
    __shared__ float red[128];
    float x0 = p[t], x1 = p[t + 128], x2 = p[t + 256];
    float m = fmaxf(x0, fmaxf(x1, x2));
    red[t] = m;
    __syncthreads();
    for (int o = 64; o > 0; o >>= 1) {
        if (t < o) red[t] = fmaxf(red[t], red[t + o]);
        __syncthreads();
    }
    m = red[0];
    __syncthreads();
    float e0 = __expf(x0 - m), e1 = __expf(x1 - m), e2 = __expf(x2 - m);
    red[t] = e0 + e1 + e2;
    __syncthreads();
    for (int o = 64; o > 0; o >>= 1) {
        if (t < o) red[t] += red[t + o];
        __syncthreads();
    }
    float inv = 1.0f / red[0];
    p[t]       = to_tf32(e0 * inv);
    p[t + 128] = to_tf32(e1 * inv);
    p[t + 256] = to_tf32(e2 * inv);
}

// ---------------------------------------------------------------------------
// K_D: tf32 mma.sync GEMM per h:  O[h][n][i] = sum_j W[i][h][j] * V[h][n][j]
// CTA tile: 128 (i) x 128 (n), K=384 in 12 chunks of 32.
// 256 threads = 8 warps in 4(m) x 2(n) grid; warp tile 32x64.
// mma.sync.m16n8k8.row.col: A row-major (i,j), B col-major == V[n][j] K-major.
// ---------------------------------------------------------------------------
#define KD_PAD 36
#define KD_CS_PAD 132
#define KD_SMEM (2 * 128 * KD_PAD * sizeof(float))   // 36864 B (Cs aliases As/Bs)

__global__ void __launch_bounds__(256) kD() {
    extern __shared__ float sm[];
    float* As = sm;                    // [128][36]
    float* Bs = sm + 128 * KD_PAD;     // [128][36]
    float* Cs = sm;                    // [64][132] reused after compute (8448 <= 9216 floats)

    const int h  = blockIdx.z;
    const int i0 = blockIdx.y * 128;
    const int n0 = blockIdx.x * 128;
    int t = threadIdx.x, lane = t & 31, wid = t >> 5;
    int wm = wid >> 1, wn = wid & 1;          // warp tile origin: (32*wm, 64*wn)
    int gid = lane >> 2, tig = lane & 3;

    float acc[2][8][4];
#pragma unroll
    for (int mf = 0; mf < 2; mf++)
#pragma unroll
        for (int nf = 0; nf < 8; nf++)
#pragma unroll
            for (int r = 0; r < 4; r++) acc[mf][nf][r] = 0.f;

    for (int ch = 0; ch < 12; ch++) {
        int j0 = ch * 32;
        // Load A (128 x 32) and B (128 x 32), 8 float4 per row.
#pragma unroll
        for (int q = 0; q < 4; q++) {
            int f = t + 256 * q;
            int row = f >> 3, cv = (f & 7) * 4;
            *(float4*)&As[row * KD_PAD + cv] =
                *(const float4*)&g_W[((size_t)(i0 + row) * HH + h) * II + j0 + cv];
            *(float4*)&Bs[row * KD_PAD + cv] =
                *(const float4*)&g_V[((size_t)h * NN + n0 + row) * II + j0 + cv];
        }
        __syncthreads();
#pragma unroll
        for (int k8 = 0; k8 < 4; k8++) {
            int kb = k8 * 8;
            uint32_t a[2][4];
#pragma unroll
            for (int mf = 0; mf < 2; mf++) {
                int r = 32 * wm + mf * 16;
                a[mf][0] = __float_as_uint(As[(r + gid    ) * KD_PAD + kb + tig    ]);
                a[mf][1] = __float_as_uint(As[(r + gid + 8) * KD_PAD + kb + tig    ]);
                a[mf][2] = __float_as_uint(As[(r + gid    ) * KD_PAD + kb + tig + 4]);
                a[mf][3] = __float_as_uint(As[(r + gid + 8) * KD_PAD + kb + tig + 4]);
            }
#pragma unroll
            for (int nf = 0; nf < 8; nf++) {
                int n = 64 * wn + nf * 8 + gid;
                uint32_t b0 = __float_as_uint(Bs[n * KD_PAD + kb + tig    ]);
                uint32_t b1 = __float_as_uint(Bs[n * KD_PAD + kb + tig + 4]);
                mma8(acc[0][nf], a[0], b0, b1);
                mma8(acc[1][nf], a[1], b0, b1);
            }
        }
        __syncthreads();
    }

    // Epilogue: stage through smem as Cs[n_local][i_local] so global writes
    // are coalesced float4 along i. Two halves of n (warp_n == half writes).
    for (int half = 0; half < 2; half++) {
        __syncthreads();
        if (wn == half) {
#pragma unroll
            for (int mf = 0; mf < 2; mf++) {
#pragma unroll
                for (int nf = 0; nf < 8; nf++) {
                    int il = 32 * wm + mf * 16 + gid;
                    int nl = nf * 8 + 2 * tig;
                    Cs[ nl      * KD_CS_PAD + il    ] = acc[mf][nf][0];
                    Cs[(nl + 1) * KD_CS_PAD + il    ] = acc[mf][nf][1];
                    Cs[ nl      * KD_CS_PAD + il + 8] = acc[mf][nf][2];
                    Cs[(nl + 1) * KD_CS_PAD + il + 8] = acc[mf][nf][3];
                }
            }
        }
        __syncthreads();
        int n  = t >> 2;
        int ic = (t & 3) * 32;
        float* dst = g_O + ((size_t)h * NN + n0 + half * 64 + n) * II + i0 + ic;
#pragma unroll
        for (int q = 0; q < 8; q++)
            *(float4*)&dst[q * 4] = *(const float4*)&Cs[n * KD_CS_PAD + ic + q * 4];
    }
}

// ---------------------------------------------------------------------------
// K_E: gate = sigmoid(msa_n @ W_gate); out = (gate * weights) @ W_out.
// Reads g_O in [h][n][i] layout (64B-contiguous per thread).
// ---------------------------------------------------------------------------
__global__ void kE(const float* __restrict__ Wg, const float* __restrict__ Wo,
                   float* __restrict__ out) {
    extern __shared__ float sm[];
    float* Wg_s = sm;              // 16384
    float* Wo_s = sm + 16384;      // 16384
    float* xn   = sm + 32768;      // 1024
    float* os   = sm + 33792;      // 4096
    int t = threadIdx.x;
    for (int idx = t; idx < 16384; idx += 256) {
        Wg_s[idx] = Wg[idx];
        Wo_s[idx] = Wo[idx];
    }
    int row0 = blockIdx.x * 16;
    {
        float4 v = *(const float4*)&g_N[(size_t)row0 * CM + t * 4];
        *(float4*)&xn[t * 4] = v;
    }
    __syncthreads();

    float acc[16];
#pragma unroll
    for (int rr = 0; rr < 16; rr++) acc[rr] = 0.f;
    for (int k = 0; k < CM; k += 4) {
        float w0 = Wg_s[(k+0) * HC + t];
        float w1 = Wg_s[(k+1) * HC + t];
        float w2 = Wg_s[(k+2) * HC + t];
        float w3 = Wg_s[(k+3) * HC + t];
#pragma unroll
        for (int rr = 0; rr < 16; rr++) {
            float4 xv = *(const float4*)&xn[rr * CM + k];
            acc[rr] += xv.x * w0 + xv.y * w1 + xv.z * w2 + xv.w * w3;
        }
    }
    // read weighted-average result: thread t = (h,c), 16 consecutive i
    {
        int h = t >> 5, c = t & 31;
        int s  = row0 / II;
        int ib = row0 % II;
        const float* Op = g_O + ((size_t)h * NN + s * CC + c) * II + ib;
        float ov[16];
#pragma unroll
        for (int q = 0; q < 4; q++) {
            float4 o4 = *(const float4*)(Op + 4*q);
            ov[4*q+0] = o4.x; ov[4*q+1] = o4.y; ov[4*q+2] = o4.z; ov[4*q+3] = o4.w;
        }
#pragma unroll
        for (int rr = 0; rr < 16; rr++) {
            float gate = 1.0f / (1.0f + __expf(-acc[rr]));
            os[rr * HC + t] = gate * ov[rr];
        }
    }
    __syncthreads();

    int n = t & 63, r0 = t >> 6;
    float a2[4] = {0.f, 0.f, 0.f, 0.f};
    for (int k = 0; k < HC; k += 4) {
        float w0 = Wo_s[(k+0) * CM + n];
        float w1 = Wo_s[(k+1) * CM + n];
        float w2 = Wo_s[(k+2) * CM + n];
        float w3 = Wo_s[(k+3) * CM + n];
#pragma unroll
        for (int q = 0; q < 4; q++) {
            float4 ov = *(const float4*)&os[(r0 + 4*q) * HC + k];
            a2[q] += ov.x * w0 + ov.y * w1 + ov.z * w2 + ov.w * w3;
        }
    }
#pragma unroll
    for (int q = 0; q < 4; q++)
        out[(size_t)(row0 + r0 + 4*q) * CM + n] = a2[q];
}

// ---------------------------------------------------------------------------
extern "C" void kernel_launch(void* const* d_in, const int* in_sizes, int n_in,
                              void* d_out, int out_size) {
    const float* msa  = (const float*)d_in[0];
    const float* pair = (const float*)d_in[1];
    const float* g1   = (const float*)d_in[2];
    const float* b1   = (const float*)d_in[3];
    const float* g2   = (const float*)d_in[4];
    const float* b2   = (const float*)d_in[5];
    const float* Wv   = (const float*)d_in[6];
    const float* Wb   = (const float*)d_in[7];
    const float* Wg   = (const float*)d_in[8];
    const float* Wo   = (const float*)d_in[9];
    float* out = (float*)d_out;

    static const size_t A_SMEM = (CM * HC + 16 * CM) * sizeof(float);           // 69632
    static const size_t E_SMEM = (16384 + 16384 + 1024 + 4096) * sizeof(float); // 151552
    cudaFuncSetAttribute(kA, cudaFuncAttributeMaxDynamicSharedMemorySize, (int)A_SMEM);
    cudaFuncSetAttribute(kE, cudaFuncAttributeMaxDynamicSharedMemorySize, (int)E_SMEM);
    cudaFuncSetAttribute(kD, cudaFuncAttributeMaxDynamicSharedMemorySize, (int)KD_SMEM);

    kA<<<SS * II / 16, 256, A_SMEM>>>(msa, g1, b1, Wv);
    kB<<<II * II / 8, 256>>>(pair, g2, b2, Wb);
    kC<<<II * HH, 128>>>();
    kD<<<dim3(NN / 128, II / 128, HH), 256, KD_SMEM>>>();
    kE<<<SS * II / 16, 256, E_SMEM>>>(Wg, Wo, out);
}

// round 7
// speedup vs baseline: 1.8287x; 1.2306x over previous
#include <cuda_runtime.h>
#include <math.h>
#include <stdint.h>

#define SS 512
#define II 384
#define CM 64
#define CZ 128
#define HH 8
#define CC 32
#define HC 256
#define NN (SS*CC)      // 16384
#define EPS 1e-5f

// Scratch (static device allocations; allowed)
__device__ float g_N[SS * II * CM];            // msa_n            [s*384+i][64]
__device__ float g_V[(size_t)HH * NN * II];    // V (tf32-rounded) [h][n=s*32+c][j=i]
__device__ float g_W[II * HH * II];            // softmax weights  [i][h][j] (tf32-rounded)
__device__ float g_O[(size_t)HH * NN * II];    // einsum result    [h][n][i]

__device__ __forceinline__ float to_tf32(float x) {
    uint32_t u;
    asm("cvt.rna.tf32.f32 %0, %1;" : "=r"(u) : "f"(x));
    return __uint_as_float(u);
}

__device__ __forceinline__ void mma8(float* d, const uint32_t* a, uint32_t b0, uint32_t b1) {
    asm volatile(
        "mma.sync.aligned.m16n8k8.row.col.f32.tf32.tf32.f32 "
        "{%0,%1,%2,%3}, {%4,%5,%6,%7}, {%8,%9}, {%0,%1,%2,%3};"
        : "+f"(d[0]), "+f"(d[1]), "+f"(d[2]), "+f"(d[3])
        : "r"(a[0]), "r"(a[1]), "r"(a[2]), "r"(a[3]), "r"(b0), "r"(b1));
}

__device__ __forceinline__ uint32_t smem_u32(const void* p) {
    uint32_t a;
    asm("{ .reg .u64 t; cvta.to.shared.u64 t, %1; cvt.u32.u64 %0, t; }" : "=r"(a) : "l"(p));
    return a;
}
#define CP16(dst, src) \
    asm volatile("cp.async.ca.shared.global [%0], [%1], 16;" :: "r"(dst), "l"(src))

// ---------------------------------------------------------------------------
// K_A: LN(msa) + V = msa_n @ W_v. 16 rows per block, 256 threads.
// ---------------------------------------------------------------------------
__global__ void kA(const float* __restrict__ msa, const float* __restrict__ gg,
                   const float* __restrict__ bb, const float* __restrict__ Wv) {
    extern __shared__ float sm[];
    float* Wv_s = sm;            // 64*256
    float* xn   = sm + CM * HC;  // 16*64
    int t = threadIdx.x;
    for (int idx = t; idx < CM * HC; idx += 256) Wv_s[idx] = Wv[idx];

    int row0 = blockIdx.x * 16;
    int r = t >> 4, l = t & 15;
    const float* x = msa + (size_t)(row0 + r) * CM + l * 4;
    float v0 = x[0], v1 = x[1], v2 = x[2], v3 = x[3];
    float sum = v0 + v1 + v2 + v3;
    float sq  = v0*v0 + v1*v1 + v2*v2 + v3*v3;
#pragma unroll
    for (int o = 8; o > 0; o >>= 1) {
        sum += __shfl_xor_sync(0xffffffffu, sum, o);
        sq  += __shfl_xor_sync(0xffffffffu, sq,  o);
    }
    float mean = sum * (1.0f / CM);
    float var  = sq * (1.0f / CM) - mean * mean;
    float rstd = rsqrtf(var + EPS);
    int k0 = l * 4;
    float n0 = (v0 - mean) * rstd * gg[k0+0] + bb[k0+0];
    float n1 = (v1 - mean) * rstd * gg[k0+1] + bb[k0+1];
    float n2 = (v2 - mean) * rstd * gg[k0+2] + bb[k0+2];
    float n3 = (v3 - mean) * rstd * gg[k0+3] + bb[k0+3];
    xn[r * CM + k0 + 0] = n0;
    xn[r * CM + k0 + 1] = n1;
    xn[r * CM + k0 + 2] = n2;
    xn[r * CM + k0 + 3] = n3;
    float* Ng = g_N + (size_t)(row0 + r) * CM + k0;
    Ng[0] = n0; Ng[1] = n1; Ng[2] = n2; Ng[3] = n3;
    __syncthreads();

    float acc[16];
#pragma unroll
    for (int rr = 0; rr < 16; rr++) acc[rr] = 0.f;
    for (int k = 0; k < CM; k += 4) {
        float w0 = Wv_s[(k+0) * HC + t];
        float w1 = Wv_s[(k+1) * HC + t];
        float w2 = Wv_s[(k+2) * HC + t];
        float w3 = Wv_s[(k+3) * HC + t];
#pragma unroll
        for (int rr = 0; rr < 16; rr++) {
            float4 xv = *(const float4*)&xn[rr * CM + k];
            acc[rr] += xv.x * w0 + xv.y * w1 + xv.z * w2 + xv.w * w3;
        }
    }
    int h = t >> 5, c = t & 31;
    int s  = row0 / II;
    int ib = row0 % II;   // 16 consecutive i values
    float* Vp = g_V + ((size_t)h * NN + s * CC + c) * II + ib;
#pragma unroll
    for (int q = 0; q < 4; q++) {
        float4 o = make_float4(to_tf32(acc[4*q+0]), to_tf32(acc[4*q+1]),
                               to_tf32(acc[4*q+2]), to_tf32(acc[4*q+3]));
        *(float4*)(Vp + 4*q) = o;
    }
}

// ---------------------------------------------------------------------------
// K_B: LN(pair) @ W_bias -> g_W[i][h][j]. One warp per (i,j) row.
// ---------------------------------------------------------------------------
__global__ void kB(const float* __restrict__ pair, const float* __restrict__ gg,
                   const float* __restrict__ bb, const float* __restrict__ Wb) {
    int warp = threadIdx.x >> 5, lane = threadIdx.x & 31;
    int row = blockIdx.x * 8 + warp;  // i*384 + j
    const float4* x4 = (const float4*)(pair + (size_t)row * CZ);
    float4 v = x4[lane];
    float sum = v.x + v.y + v.z + v.w;
    float sq  = v.x*v.x + v.y*v.y + v.z*v.z + v.w*v.w;
#pragma unroll
    for (int o = 16; o > 0; o >>= 1) {
        sum += __shfl_xor_sync(0xffffffffu, sum, o);
        sq  += __shfl_xor_sync(0xffffffffu, sq,  o);
    }
    float mean = sum * (1.0f / CZ);
    float var  = sq * (1.0f / CZ) - mean * mean;
    float rstd = rsqrtf(var + EPS);
    int k0 = lane * 4;
    float n0 = (v.x - mean) * rstd * gg[k0+0] + bb[k0+0];
    float n1 = (v.y - mean) * rstd * gg[k0+1] + bb[k0+1];
    float n2 = (v.z - mean) * rstd * gg[k0+2] + bb[k0+2];
    float n3 = (v.w - mean) * rstd * gg[k0+3] + bb[k0+3];
    float ph[HH];
#pragma unroll
    for (int h = 0; h < HH; h++) {
        ph[h] = n0 * Wb[(k0+0)*HH + h] + n1 * Wb[(k0+1)*HH + h]
              + n2 * Wb[(k0+2)*HH + h] + n3 * Wb[(k0+3)*HH + h];
    }
#pragma unroll
    for (int h = 0; h < HH; h++) {
#pragma unroll
        for (int o = 16; o > 0; o >>= 1)
            ph[h] += __shfl_xor_sync(0xffffffffu, ph[h], o);
    }
    if (lane == 0) {
        int i = row / II, j = row % II;
#pragma unroll
        for (int h = 0; h < HH; h++)
            g_W[((size_t)i * HH + h) * II + j] = ph[h];
    }
}

// ---------------------------------------------------------------------------
// K_C: in-place softmax over j for each (i,h); output tf32-rounded.
// ---------------------------------------------------------------------------
__global__ void kC() {
    int row = blockIdx.x;  // i*8 + h
    float* p = g_W + (size_t)row * II;
    int t = threadIdx.x;
    __shared__ float red[128];
    float x0 = p[t], x1 = p[t + 128], x2 = p[t + 256];
    float m = fmaxf(x0, fmaxf(x1, x2));
    red[t] = m;
    __syncthreads();
    for (int o = 64; o > 0; o >>= 1) {
        if (t < o) red[t] = fmaxf(red[t], red[t + o]);
        __syncthreads();
    }
    m = red[0];
    __syncthreads();
    float e0 = __expf(x0 - m), e1 = __expf(x1 - m), e2 = __expf(x2 - m);
    red[t] = e0 + e1 + e2;
    __syncthreads();
    for (int o = 64; o > 0; o >>= 1) {
        if (t < o) red[t] += red[t + o];
        __syncthreads();
    }
    float inv = 1.0f / red[0];
    p[t]       = to_tf32(e0 * inv);
    p[t + 128] = to_tf32(e1 * inv);
    p[t + 256] = to_tf32(e2 * inv);
}

// ---------------------------------------------------------------------------
// K_D: tf32 mma.sync GEMM per h, 2-stage cp.async pipeline.
// O[h][n][i] = sum_j W[i][h][j] * V[h][n][j]; CTA tile 128(i) x 128(n), 12 K-chunks.
// ---------------------------------------------------------------------------
#define KD_PAD 36
#define KD_STG (128 * KD_PAD)                      // floats per matrix per stage
#define KD_CS_PAD 132
#define KD_SMEM (4 * KD_STG * sizeof(float))       // 2 stages x (A+B) = 73728 B

__global__ void __launch_bounds__(256, 2) kD() {
    extern __shared__ float sm[];
    float* Cs = sm;   // epilogue staging aliases stage buffers (33792 <= 73728 B)

    const int h  = blockIdx.z;
    const int i0 = blockIdx.y * 128;
    const int n0 = blockIdx.x * 128;
    int t = threadIdx.x, lane = t & 31, wid = t >> 5;
    int wm = wid >> 1, wn = wid & 1;
    int gid = lane >> 2, tig = lane & 3;
    uint32_t smb = smem_u32(sm);

    float acc[2][8][4];
#pragma unroll
    for (int mf = 0; mf < 2; mf++)
#pragma unroll
        for (int nf = 0; nf < 8; nf++)
#pragma unroll
            for (int r = 0; r < 4; r++) acc[mf][nf][r] = 0.f;

    // prefetch chunk ch into buffer buf
    auto prefetch = [&](int ch, int buf) {
        uint32_t a_base = smb + (uint32_t)(buf * 2 * KD_STG) * 4u;
        uint32_t b_base = a_base + (uint32_t)KD_STG * 4u;
        int j0 = ch * 32;
#pragma unroll
        for (int q = 0; q < 4; q++) {
            int f = t + 256 * q;
            int row = f >> 3, cv = (f & 7) * 4;
            CP16(a_base + (uint32_t)(row * KD_PAD + cv) * 4u,
                 g_W + ((size_t)(i0 + row) * HH + h) * II + j0 + cv);
            CP16(b_base + (uint32_t)(row * KD_PAD + cv) * 4u,
                 g_V + ((size_t)h * NN + n0 + row) * II + j0 + cv);
        }
        asm volatile("cp.async.commit_group;" ::: "memory");
    };

    prefetch(0, 0);

    for (int ch = 0; ch < 12; ch++) {
        if (ch < 11) {
            prefetch(ch + 1, (ch + 1) & 1);
            asm volatile("cp.async.wait_group 1;" ::: "memory");
        } else {
            asm volatile("cp.async.wait_group 0;" ::: "memory");
        }
        __syncthreads();
        const float* As = sm + (ch & 1) * 2 * KD_STG;
        const float* Bs = As + KD_STG;
#pragma unroll
        for (int k8 = 0; k8 < 4; k8++) {
            int kb = k8 * 8;
            uint32_t a[2][4];
#pragma unroll
            for (int mf = 0; mf < 2; mf++) {
                int r = 32 * wm + mf * 16;
                a[mf][0] = __float_as_uint(As[(r + gid    ) * KD_PAD + kb + tig    ]);
                a[mf][1] = __float_as_uint(As[(r + gid + 8) * KD_PAD + kb + tig    ]);
                a[mf][2] = __float_as_uint(As[(r + gid    ) * KD_PAD + kb + tig + 4]);
                a[mf][3] = __float_as_uint(As[(r + gid + 8) * KD_PAD + kb + tig + 4]);
            }
#pragma unroll
            for (int nf = 0; nf < 8; nf++) {
                int n = 64 * wn + nf * 8 + gid;
                uint32_t b0 = __float_as_uint(Bs[n * KD_PAD + kb + tig    ]);
                uint32_t b1 = __float_as_uint(Bs[n * KD_PAD + kb + tig + 4]);
                mma8(acc[0][nf], a[0], b0, b1);
                mma8(acc[1][nf], a[1], b0, b1);
            }
        }
        __syncthreads();
    }

    // Epilogue: stage through smem as Cs[n_local][i_local], coalesced writes.
    for (int half = 0; half < 2; half++) {
        __syncthreads();
        if (wn == half) {
#pragma unroll
            for (int mf = 0; mf < 2; mf++) {
#pragma unroll
                for (int nf = 0; nf < 8; nf++) {
                    int il = 32 * wm + mf * 16 + gid;
                    int nl = nf * 8 + 2 * tig;
                    Cs[ nl      * KD_CS_PAD + il    ] = acc[mf][nf][0];
                    Cs[(nl + 1) * KD_CS_PAD + il    ] = acc[mf][nf][1];
                    Cs[ nl      * KD_CS_PAD + il + 8] = acc[mf][nf][2];
                    Cs[(nl + 1) * KD_CS_PAD + il + 8] = acc[mf][nf][3];
                }
            }
        }
        __syncthreads();
        int n  = t >> 2;
        int ic = (t & 3) * 32;
        float* dst = g_O + ((size_t)h * NN + n0 + half * 64 + n) * II + i0 + ic;
#pragma unroll
        for (int q = 0; q < 8; q++)
            *(float4*)&dst[q * 4] = *(const float4*)&Cs[n * KD_CS_PAD + ic + q * 4];
    }
}

// ---------------------------------------------------------------------------
// K_E (mma): per block 64 rows (one s, 64 consecutive i).
// Phase1: G = X @ Wg (64x256x64), sigmoid, gather O, gated -> gs (tf32).
// Phase2: out = gs @ Wo (64x64x256), coalesced float2 stores.
// ---------------------------------------------------------------------------
#define WG_ST 66
#define WO_ST 258
#define X_ST  66
#define GS_ST 258
#define E_OFF_WG 0
#define E_OFF_WO (E_OFF_WG + 256 * WG_ST)          // 16896
#define E_OFF_X  (E_OFF_WO + 64 * WO_ST)           // 33408
#define E_OFF_GS (E_OFF_X  + 64 * X_ST)            // 37632
#define E_SMEM   ((E_OFF_GS + 64 * GS_ST) * sizeof(float))  // 216576 B

__global__ void __launch_bounds__(256) kE(const float* __restrict__ Wg,
                                          const float* __restrict__ Wo,
                                          float* __restrict__ out) {
    extern __shared__ float sm[];
    float* Wg_t = sm + E_OFF_WG;   // [n=256][k=64]
    float* Wo_t = sm + E_OFF_WO;   // [n=64][k=256]
    float* Xs   = sm + E_OFF_X;    // [m=64][k=64]
    float* gs   = sm + E_OFF_GS;   // [m=64][k=256]

    int t = threadIdx.x, lane = t & 31, wid = t >> 5;
    int gid = lane >> 2, tig = lane & 3;
    int row0 = blockIdx.x * 64;
    int s = row0 / II, i0g = row0 % II;

    // Load + transpose weights (tf32-rounded)
#pragma unroll
    for (int q = 0; q < 16; q++) {
        int idx = t + 256 * q;
        {   // Wg [64][256] -> Wg_t [n][k]
            int k = idx >> 6, n4 = (idx & 63) * 4;
            float4 v = *(const float4*)(Wg + (size_t)k * HC + n4);
            Wg_t[(n4+0) * WG_ST + k] = to_tf32(v.x);
            Wg_t[(n4+1) * WG_ST + k] = to_tf32(v.y);
            Wg_t[(n4+2) * WG_ST + k] = to_tf32(v.z);
            Wg_t[(n4+3) * WG_ST + k] = to_tf32(v.w);
        }
        {   // Wo [256][64] -> Wo_t [n][k]
            int k = idx >> 4, n4 = (idx & 15) * 4;
            float4 v = *(const float4*)(Wo + (size_t)k * CM + n4);
            Wo_t[(n4+0) * WO_ST + k] = to_tf32(v.x);
            Wo_t[(n4+1) * WO_ST + k] = to_tf32(v.y);
            Wo_t[(n4+2) * WO_ST + k] = to_tf32(v.z);
            Wo_t[(n4+3) * WO_ST + k] = to_tf32(v.w);
        }
    }
#pragma unroll
    for (int q = 0; q < 4; q++) {   // X rows [m][k], tf32
        int idx = t + 256 * q;
        int m = idx >> 4, k4 = (idx & 15) * 4;
        float4 v = *(const float4*)(g_N + (size_t)(row0 + m) * CM + k4);
        Xs[m * X_ST + k4 + 0] = to_tf32(v.x);
        Xs[m * X_ST + k4 + 1] = to_tf32(v.y);
        Xs[m * X_ST + k4 + 2] = to_tf32(v.z);
        Xs[m * X_ST + k4 + 3] = to_tf32(v.w);
    }
    __syncthreads();

    // Phase 1: warps 2(m) x 4(n); warp tile 32 x 64
    {
        int wm = wid & 1, wn = wid >> 1;
        float acc[2][8][4];
#pragma unroll
        for (int mf = 0; mf < 2; mf++)
#pragma unroll
            for (int nf = 0; nf < 8; nf++)
#pragma unroll
                for (int r = 0; r < 4; r++) acc[mf][nf][r] = 0.f;

#pragma unroll
        for (int k8 = 0; k8 < 8; k8++) {
            int kb = k8 * 8;
            uint32_t a[2][4];
#pragma unroll
            for (int mf = 0; mf < 2; mf++) {
                int r = wm * 32 + mf * 16;
                a[mf][0] = __float_as_uint(Xs[(r + gid    ) * X_ST + kb + tig    ]);
                a[mf][1] = __float_as_uint(Xs[(r + gid + 8) * X_ST + kb + tig    ]);
                a[mf][2] = __float_as_uint(Xs[(r + gid    ) * X_ST + kb + tig + 4]);
                a[mf][3] = __float_as_uint(Xs[(r + gid + 8) * X_ST + kb + tig + 4]);
            }
#pragma unroll
            for (int nf = 0; nf < 8; nf++) {
                int n = wn * 64 + nf * 8 + gid;
                uint32_t b0 = __float_as_uint(Wg_t[n * WG_ST + kb + tig    ]);
                uint32_t b1 = __float_as_uint(Wg_t[n * WG_ST + kb + tig + 4]);
                mma8(acc[0][nf], a[0], b0, b1);
                mma8(acc[1][nf], a[1], b0, b1);
            }
        }
        // sigmoid, gather O, store gated products
#pragma unroll
        for (int mf = 0; mf < 2; mf++) {
#pragma unroll
            for (int nf = 0; nf < 8; nf++) {
                int mb  = wm * 32 + mf * 16 + gid;
                int col = wn * 64 + nf * 8 + 2 * tig;
#pragma unroll
                for (int r = 0; r < 4; r++) {
                    int m  = mb + ((r >= 2) ? 8 : 0);
                    int cl = col + (r & 1);
                    float gate = 1.0f / (1.0f + __expf(-acc[mf][nf][r]));
                    int hh = cl >> 5, cc2 = cl & 31;
                    float ov = g_O[((size_t)hh * NN + s * CC + cc2) * II + i0g + m];
                    gs[m * GS_ST + cl] = to_tf32(gate * ov);
                }
            }
        }
    }
    __syncthreads();

    // Phase 2: warps 4(m) x 2(n); warp tile 16 x 32; K = 256
    {
        int wm2 = wid >> 1, wn2 = wid & 1;
        float acc2[4][4];
#pragma unroll
        for (int nf = 0; nf < 4; nf++)
#pragma unroll
            for (int r = 0; r < 4; r++) acc2[nf][r] = 0.f;

#pragma unroll 4
        for (int k8 = 0; k8 < 32; k8++) {
            int kb = k8 * 8;
            int r = wm2 * 16;
            uint32_t a[4];
            a[0] = __float_as_uint(gs[(r + gid    ) * GS_ST + kb + tig    ]);
            a[1] = __float_as_uint(gs[(r + gid + 8) * GS_ST + kb + tig    ]);
            a[2] = __float_as_uint(gs[(r + gid    ) * GS_ST + kb + tig + 4]);
            a[3] = __float_as_uint(gs[(r + gid + 8) * GS_ST + kb + tig + 4]);
#pragma unroll
            for (int nf = 0; nf < 4; nf++) {
                int n = wn2 * 32 + nf * 8 + gid;
                uint32_t b0 = __float_as_uint(Wo_t[n * WO_ST + kb + tig    ]);
                uint32_t b1 = __float_as_uint(Wo_t[n * WO_ST + kb + tig + 4]);
                mma8(acc2[nf], a, b0, b1);
            }
        }
#pragma unroll
        for (int nf = 0; nf < 4; nf++) {
            int m   = wm2 * 16 + gid;
            int col = wn2 * 32 + nf * 8 + 2 * tig;
            float2 v0 = make_float2(acc2[nf][0], acc2[nf][1]);
            float2 v1 = make_float2(acc2[nf][2], acc2[nf][3]);
            *(float2*)&out[(size_t)(row0 + m    ) * CM + col] = v0;
            *(float2*)&out[(size_t)(row0 + m + 8) * CM + col] = v1;
        }
    }
}

// ---------------------------------------------------------------------------
extern "C" void kernel_launch(void* const* d_in, const int* in_sizes, int n_in,
                              void* d_out, int out_size) {
    const float* msa  = (const float*)d_in[0];
    const float* pair = (const float*)d_in[1];
    const float* g1   = (const float*)d_in[2];
    const float* b1   = (const float*)d_in[3];
    const float* g2   = (const float*)d_in[4];
    const float* b2   = (const float*)d_in[5];
    const float* Wv   = (const float*)d_in[6];
    const float* Wb   = (const float*)d_in[7];
    const float* Wg   = (const float*)d_in[8];
    const float* Wo   = (const float*)d_in[9];
    float* out = (float*)d_out;

    static const size_t A_SMEM = (CM * HC + 16 * CM) * sizeof(float);  // 69632
    cudaFuncSetAttribute(kA, cudaFuncAttributeMaxDynamicSharedMemorySize, (int)A_SMEM);
    cudaFuncSetAttribute(kD, cudaFuncAttributeMaxDynamicSharedMemorySize, (int)KD_SMEM);
    cudaFuncSetAttribute(kE, cudaFuncAttributeMaxDynamicSharedMemorySize, (int)E_SMEM);

    kA<<<SS * II / 16, 256, A_SMEM>>>(msa, g1, b1, Wv);
    kB<<<II * II / 8, 256>>>(pair, g2, b2, Wb);
    kC<<<II * HH, 128>>>();
    kD<<<dim3(NN / 128, II / 128, HH), 256, KD_SMEM>>>();
    kE<<<SS * II / 64, 256, E_SMEM>>>(Wg, Wo, out);
}

// round 9
// speedup vs baseline: 2.1031x; 1.1500x over previous
#include <cuda_runtime.h>
#include <math.h>
#include <stdint.h>

#define SS 512
#define II 384
#define CM 64
#define CZ 128
#define HH 8
#define CC 32
#define HC 256
#define NN (SS*CC)      // 16384
#define EPS 1e-5f

// Scratch (static device allocations; allowed)
__device__ float g_N[SS * II * CM];            // msa_n (tf32)     [s*384+i][64]
__device__ float g_V[(size_t)HH * NN * II];    // V (tf32)         [h][n=s*32+c][j=i]
__device__ float g_W[II * HH * II];            // softmax weights  [i][h][j] (tf32)
__device__ float g_O[(size_t)HH * NN * II];    // einsum result    [h][n][i]

__device__ __forceinline__ float to_tf32(float x) {
    uint32_t u;
    asm("cvt.rna.tf32.f32 %0, %1;" : "=r"(u) : "f"(x));
    return __uint_as_float(u);
}

__device__ __forceinline__ void mma8(float* d, const uint32_t* a, uint32_t b0, uint32_t b1) {
    asm volatile(
        "mma.sync.aligned.m16n8k8.row.col.f32.tf32.tf32.f32 "
        "{%0,%1,%2,%3}, {%4,%5,%6,%7}, {%8,%9}, {%0,%1,%2,%3};"
        : "+f"(d[0]), "+f"(d[1]), "+f"(d[2]), "+f"(d[3])
        : "r"(a[0]), "r"(a[1]), "r"(a[2]), "r"(a[3]), "r"(b0), "r"(b1));
}

__device__ __forceinline__ uint32_t smem_u32(const void* p) {
    uint32_t a;
    asm("{ .reg .u64 t; cvta.to.shared.u64 t, %1; cvt.u32.u64 %0, t; }" : "=r"(a) : "l"(p));
    return a;
}
#define CP16(dst, src) \
    asm volatile("cp.async.ca.shared.global [%0], [%1], 16;" :: "r"(dst), "l"(src))

// ---------------------------------------------------------------------------
// K_A: LN(msa) only -> g_N (tf32-rounded). 16 rows per block, 256 threads.
// ---------------------------------------------------------------------------
__global__ void kA(const float* __restrict__ msa, const float* __restrict__ gg,
                   const float* __restrict__ bb) {
    int t = threadIdx.x;
    int row0 = blockIdx.x * 16;
    int r = t >> 4, l = t & 15;
    const float* x = msa + (size_t)(row0 + r) * CM + l * 4;
    float v0 = x[0], v1 = x[1], v2 = x[2], v3 = x[3];
    float sum = v0 + v1 + v2 + v3;
    float sq  = v0*v0 + v1*v1 + v2*v2 + v3*v3;
#pragma unroll
    for (int o = 8; o > 0; o >>= 1) {
        sum += __shfl_xor_sync(0xffffffffu, sum, o);
        sq  += __shfl_xor_sync(0xffffffffu, sq,  o);
    }
    float mean = sum * (1.0f / CM);
    float var  = sq * (1.0f / CM) - mean * mean;
    float rstd = rsqrtf(var + EPS);
    int k0 = l * 4;
    float4 o4;
    o4.x = to_tf32((v0 - mean) * rstd * gg[k0+0] + bb[k0+0]);
    o4.y = to_tf32((v1 - mean) * rstd * gg[k0+1] + bb[k0+1]);
    o4.z = to_tf32((v2 - mean) * rstd * gg[k0+2] + bb[k0+2]);
    o4.w = to_tf32((v3 - mean) * rstd * gg[k0+3] + bb[k0+3]);
    *(float4*)(g_N + (size_t)(row0 + r) * CM + k0) = o4;
}

// ---------------------------------------------------------------------------
// K_AV: V = g_N @ Wv via mma. M-tile 128 (rows = s*II+i), N=256, K=64.
// 256 threads, 8 warps (2m x 4n), warp tile 64x64.
// Epilogue writes g_V[h][s*32+c][i] (transposed, tf32) via smem staging.
// ---------------------------------------------------------------------------
#define AV_ST_A 68
#define AV_ST_B 65
#define AV_OFF_B (128 * AV_ST_A)
#define AV_SMEM ((128 * AV_ST_A + 256 * AV_ST_B) * sizeof(float))  // 101376 B
#define AV_CS 132

__global__ void __launch_bounds__(256) kAV(const float* __restrict__ Wv) {
    extern __shared__ float sm[];
    float* As = sm;
    float* Bs = sm + AV_OFF_B;
    float* Cs = sm;   // epilogue alias (64*132 = 8448 floats <= 8704)

    int t = threadIdx.x, lane = t & 31, wid = t >> 5;
    int gid = lane >> 2, tig = lane & 3;
    int wm = wid >> 2, wn = wid & 3;
    int row0 = blockIdx.x * 128;
    int s = row0 / II, i0 = row0 % II;

    // A: 128 x 64 from g_N (already tf32)
#pragma unroll
    for (int q = 0; q < 8; q++) {
        int idx = t + 256 * q;
        int m = idx >> 4, k4 = (idx & 15) * 4;
        *(float4*)&As[m * AV_ST_A + k4] =
            *(const float4*)(g_N + (size_t)(row0 + m) * CM + k4);
    }
    // B: Wv [k=64][n=256] -> Bs[n][k], tf32. Coalesced gmem, conflict-free smem.
    {
        int n = t;
#pragma unroll
        for (int k = 0; k < CM; k++)
            Bs[n * AV_ST_B + k] = to_tf32(Wv[(size_t)k * HC + n]);
    }
    __syncthreads();

    float acc[4][8][4];
#pragma unroll
    for (int mf = 0; mf < 4; mf++)
#pragma unroll
        for (int nf = 0; nf < 8; nf++)
#pragma unroll
            for (int r = 0; r < 4; r++) acc[mf][nf][r] = 0.f;

#pragma unroll
    for (int k8 = 0; k8 < 8; k8++) {
        int kb = k8 * 8;
        uint32_t a[4][4];
#pragma unroll
        for (int mf = 0; mf < 4; mf++) {
            int r = 64 * wm + mf * 16;
            a[mf][0] = __float_as_uint(As[(r + gid    ) * AV_ST_A + kb + tig    ]);
            a[mf][1] = __float_as_uint(As[(r + gid + 8) * AV_ST_A + kb + tig    ]);
            a[mf][2] = __float_as_uint(As[(r + gid    ) * AV_ST_A + kb + tig + 4]);
            a[mf][3] = __float_as_uint(As[(r + gid + 8) * AV_ST_A + kb + tig + 4]);
        }
#pragma unroll
        for (int nf = 0; nf < 8; nf++) {
            int n = 64 * wn + nf * 8 + gid;
            uint32_t b0 = __float_as_uint(Bs[n * AV_ST_B + kb + tig    ]);
            uint32_t b1 = __float_as_uint(Bs[n * AV_ST_B + kb + tig + 4]);
#pragma unroll
            for (int mf = 0; mf < 4; mf++) mma8(acc[mf][nf], a[mf], b0, b1);
        }
    }

    // Epilogue: 4 quarters of 64 columns; stage Cs[col][i], write coalesced.
    for (int qq = 0; qq < 4; qq++) {
        __syncthreads();
        if (wn == qq) {
#pragma unroll
            for (int mf = 0; mf < 4; mf++) {
#pragma unroll
                for (int nf = 0; nf < 8; nf++) {
                    int il = 64 * wm + mf * 16 + gid;
                    int nl = nf * 8 + 2 * tig;
                    Cs[ nl      * AV_CS + il    ] = to_tf32(acc[mf][nf][0]);
                    Cs[(nl + 1) * AV_CS + il    ] = to_tf32(acc[mf][nf][1]);
                    Cs[ nl      * AV_CS + il + 8] = to_tf32(acc[mf][nf][2]);
                    Cs[(nl + 1) * AV_CS + il + 8] = to_tf32(acc[mf][nf][3]);
                }
            }
        }
        __syncthreads();
        int c0 = t >> 2;            // 0..63 column within quarter
        int ic = (t & 3) * 32;      // i chunk
        int cl = qq * 64 + c0;
        int hh = cl >> 5, cc = cl & 31;
        float* dst = g_V + ((size_t)hh * NN + s * CC + cc) * II + i0 + ic;
#pragma unroll
        for (int q2 = 0; q2 < 8; q2++)
            *(float4*)&dst[q2 * 4] = *(const float4*)&Cs[c0 * AV_CS + ic + q2 * 4];
    }
}

// ---------------------------------------------------------------------------
// K_B: LN(pair) @ W_bias -> g_W[i][h][j]. One warp per (i,j) row.
// ---------------------------------------------------------------------------
__global__ void kB(const float* __restrict__ pair, const float* __restrict__ gg,
                   const float* __restrict__ bb, const float* __restrict__ Wb) {
    int warp = threadIdx.x >> 5, lane = threadIdx.x & 31;
    int row = blockIdx.x * 8 + warp;  // i*384 + j
    const float4* x4 = (const float4*)(pair + (size_t)row * CZ);
    float4 v = x4[lane];
    float sum = v.x + v.y + v.z + v.w;
    float sq  = v.x*v.x + v.y*v.y + v.z*v.z + v.w*v.w;
#pragma unroll
    for (int o = 16; o > 0; o >>= 1) {
        sum += __shfl_xor_sync(0xffffffffu, sum, o);
        sq  += __shfl_xor_sync(0xffffffffu, sq,  o);
    }
    float mean = sum * (1.0f / CZ);
    float var  = sq * (1.0f / CZ) - mean * mean;
    float rstd = rsqrtf(var + EPS);
    int k0 = lane * 4;
    float n0 = (v.x - mean) * rstd * gg[k0+0] + bb[k0+0];
    float n1 = (v.y - mean) * rstd * gg[k0+1] + bb[k0+1];
    float n2 = (v.z - mean) * rstd * gg[k0+2] + bb[k0+2];
    float n3 = (v.w - mean) * rstd * gg[k0+3] + bb[k0+3];
    float ph[HH];
#pragma unroll
    for (int h = 0; h < HH; h++) {
        ph[h] = n0 * Wb[(k0+0)*HH + h] + n1 * Wb[(k0+1)*HH + h]
              + n2 * Wb[(k0+2)*HH + h] + n3 * Wb[(k0+3)*HH + h];
    }
#pragma unroll
    for (int h = 0; h < HH; h++) {
#pragma unroll
        for (int o = 16; o > 0; o >>= 1)
            ph[h] += __shfl_xor_sync(0xffffffffu, ph[h], o);
    }
    if (lane == 0) {
        int i = row / II, j = row % II;
#pragma unroll
        for (int h = 0; h < HH; h++)
            g_W[((size_t)i * HH + h) * II + j] = ph[h];
    }
}

// ---------------------------------------------------------------------------
// K_C: in-place softmax over j for each (i,h); output tf32-rounded.
// ---------------------------------------------------------------------------
__global__ void kC() {
    int row = blockIdx.x;  // i*8 + h
    float* p = g_W + (size_t)row * II;
    int t = threadIdx.x;
    __shared__ float red[128];
    float x0 = p[t], x1 = p[t + 128], x2 = p[t + 256];
    float m = fmaxf(x0, fmaxf(x1, x2));
    red[t] = m;
    __syncthreads();
    for (int o = 64; o > 0; o >>= 1) {
        if (t < o) red[t] = fmaxf(red[t], red[t + o]);
        __syncthreads();
    }
    m = red[0];
    __syncthreads();
    float e0 = __expf(x0 - m), e1 = __expf(x1 - m), e2 = __expf(x2 - m);
    red[t] = e0 + e1 + e2;
    __syncthreads();
    for (int o = 64; o > 0; o >>= 1) {
        if (t < o) red[t] += red[t + o];
        __syncthreads();
    }
    float inv = 1.0f / red[0];
    p[t]       = to_tf32(e0 * inv);
    p[t + 128] = to_tf32(e1 * inv);
    p[t + 256] = to_tf32(e2 * inv);
}

// ---------------------------------------------------------------------------
// K_D: tf32 mma GEMM per h, 2-stage cp.async, 128 threads, 4 warps (2x2),
// warp tile 64x64. O[h][n][i] = sum_j W[i][h][j] * V[h][n][j].
// ---------------------------------------------------------------------------
#define KD_PAD 36
#define KD_STG (128 * KD_PAD)
#define KD_CS_PAD 132
#define KD_SMEM (4 * KD_STG * sizeof(float))   // 73728 B

__global__ void __launch_bounds__(128, 2) kD() {
    extern __shared__ float sm[];
    float* Cs = sm;

    const int h  = blockIdx.z;
    const int i0 = blockIdx.y * 128;
    const int n0 = blockIdx.x * 128;
    int t = threadIdx.x, lane = t & 31, wid = t >> 5;
    int wm = wid >> 1, wn = wid & 1;
    int gid = lane >> 2, tig = lane & 3;
    uint32_t smb = smem_u32(sm);

    float acc[4][8][4];
#pragma unroll
    for (int mf = 0; mf < 4; mf++)
#pragma unroll
        for (int nf = 0; nf < 8; nf++)
#pragma unroll
            for (int r = 0; r < 4; r++) acc[mf][nf][r] = 0.f;

    auto prefetch = [&](int ch, int buf) {
        uint32_t a_base = smb + (uint32_t)(buf * 2 * KD_STG) * 4u;
        uint32_t b_base = a_base + (uint32_t)KD_STG * 4u;
        int j0 = ch * 32;
#pragma unroll
        for (int q = 0; q < 8; q++) {
            int f = t + 128 * q;
            int row = f >> 3, cv = (f & 7) * 4;
            CP16(a_base + (uint32_t)(row * KD_PAD + cv) * 4u,
                 g_W + ((size_t)(i0 + row) * HH + h) * II + j0 + cv);
            CP16(b_base + (uint32_t)(row * KD_PAD + cv) * 4u,
                 g_V + ((size_t)h * NN + n0 + row) * II + j0 + cv);
        }
        asm volatile("cp.async.commit_group;" ::: "memory");
    };

    prefetch(0, 0);

    for (int ch = 0; ch < 12; ch++) {
        if (ch < 11) {
            prefetch(ch + 1, (ch + 1) & 1);
            asm volatile("cp.async.wait_group 1;" ::: "memory");
        } else {
            asm volatile("cp.async.wait_group 0;" ::: "memory");
        }
        __syncthreads();
        const float* As = sm + (ch & 1) * 2 * KD_STG;
        const float* Bs = As + KD_STG;
#pragma unroll
        for (int k8 = 0; k8 < 4; k8++) {
            int kb = k8 * 8;
            uint32_t a[4][4];
#pragma unroll
            for (int mf = 0; mf < 4; mf++) {
                int r = 64 * wm + mf * 16;
                a[mf][0] = __float_as_uint(As[(r + gid    ) * KD_PAD + kb + tig    ]);
                a[mf][1] = __float_as_uint(As[(r + gid + 8) * KD_PAD + kb + tig    ]);
                a[mf][2] = __float_as_uint(As[(r + gid    ) * KD_PAD + kb + tig + 4]);
                a[mf][3] = __float_as_uint(As[(r + gid + 8) * KD_PAD + kb + tig + 4]);
            }
#pragma unroll
            for (int nf = 0; nf < 8; nf++) {
                int n = 64 * wn + nf * 8 + gid;
                uint32_t b0 = __float_as_uint(Bs[n * KD_PAD + kb + tig    ]);
                uint32_t b1 = __float_as_uint(Bs[n * KD_PAD + kb + tig + 4]);
#pragma unroll
                for (int mf = 0; mf < 4; mf++) mma8(acc[mf][nf], a[mf], b0, b1);
            }
        }
        __syncthreads();
    }

    // Epilogue: halves of 64 n-columns; stage Cs[n_local][i_local].
    for (int half = 0; half < 2; half++) {
        __syncthreads();
        if (wn == half) {
#pragma unroll
            for (int mf = 0; mf < 4; mf++) {
#pragma unroll
                for (int nf = 0; nf < 8; nf++) {
                    int il = 64 * wm + mf * 16 + gid;
                    int nl = nf * 8 + 2 * tig;
                    Cs[ nl      * KD_CS_PAD + il    ] = acc[mf][nf][0];
                    Cs[(nl + 1) * KD_CS_PAD + il    ] = acc[mf][nf][1];
                    Cs[ nl      * KD_CS_PAD + il + 8] = acc[mf][nf][2];
                    Cs[(nl + 1) * KD_CS_PAD + il + 8] = acc[mf][nf][3];
                }
            }
        }
        __syncthreads();
        int n  = t >> 1;
        int ic = (t & 1) * 64;
        float* dst = g_O + ((size_t)h * NN + n0 + half * 64 + n) * II + i0 + ic;
#pragma unroll
        for (int q = 0; q < 16; q++)
            *(float4*)&dst[q * 4] = *(const float4*)&Cs[n * KD_CS_PAD + ic + q * 4];
    }
}

// ---------------------------------------------------------------------------
// K_E (persistent): weights loaded+transposed once per block; loop row-tiles.
// Phase1: G = X @ Wg (64x256x64), sigmoid, gather O -> gs (tf32).
// Phase2: out = gs @ Wo (64x64x256).
// ---------------------------------------------------------------------------
#define WG_ST 66
#define WO_ST 258
#define X_ST  66
#define GS_ST 258
#define E_OFF_WG 0
#define E_OFF_WO (E_OFF_WG + 256 * WG_ST)          // 16896
#define E_OFF_X  (E_OFF_WO + 64 * WO_ST)           // 33408
#define E_OFF_GS (E_OFF_X  + 64 * X_ST)            // 37632
#define E_SMEM   ((E_OFF_GS + 64 * GS_ST) * sizeof(float))  // 216576 B
#define E_GRID 152
#define E_TILES (SS * II / 64)                      // 3072

__global__ void __launch_bounds__(256) kE(const float* __restrict__ Wg,
                                          const float* __restrict__ Wo,
                                          float* __restrict__ out) {
    extern __shared__ float sm[];
    float* Wg_t = sm + E_OFF_WG;   // [n=256][k=64]
    float* Wo_t = sm + E_OFF_WO;   // [n=64][k=256]
    float* Xs   = sm + E_OFF_X;    // [m=64][k=64]
    float* gs   = sm + E_OFF_GS;   // [m=64][k=256]

    int t = threadIdx.x, lane = t & 31, wid = t >> 5;
    int gid = lane >> 2, tig = lane & 3;

    // One-time weight load + transpose (tf32)
#pragma unroll
    for (int q = 0; q < 16; q++) {
        int idx = t + 256 * q;
        {   // Wg [64][256] -> Wg_t [n][k]
            int k = idx >> 6, n4 = (idx & 63) * 4;
            float4 v = *(const float4*)(Wg + (size_t)k * HC + n4);
            Wg_t[(n4+0) * WG_ST + k] = to_tf32(v.x);
            Wg_t[(n4+1) * WG_ST + k] = to_tf32(v.y);
            Wg_t[(n4+2) * WG_ST + k] = to_tf32(v.z);
            Wg_t[(n4+3) * WG_ST + k] = to_tf32(v.w);
        }
        {   // Wo [256][64] -> Wo_t [n][k]
            int k = idx >> 4, n4 = (idx & 15) * 4;
            float4 v = *(const float4*)(Wo + (size_t)k * CM + n4);
            Wo_t[(n4+0) * WO_ST + k] = to_tf32(v.x);
            Wo_t[(n4+1) * WO_ST + k] = to_tf32(v.y);
            Wo_t[(n4+2) * WO_ST + k] = to_tf32(v.z);
            Wo_t[(n4+3) * WO_ST + k] = to_tf32(v.w);
        }
    }
    __syncthreads();

    for (int tile = blockIdx.x; tile < E_TILES; tile += E_GRID) {
        int row0 = tile * 64;
        int s = tile / 6, i0g = (tile % 6) * 64;

        // Load X rows [m][k] (g_N already tf32)
#pragma unroll
        for (int q = 0; q < 4; q++) {
            int idx = t + 256 * q;
            int m = idx >> 4, k4 = (idx & 15) * 4;
            float4 v = *(const float4*)(g_N + (size_t)(row0 + m) * CM + k4);
            Xs[m * X_ST + k4 + 0] = v.x;
            Xs[m * X_ST + k4 + 1] = v.y;
            Xs[m * X_ST + k4 + 2] = v.z;
            Xs[m * X_ST + k4 + 3] = v.w;
        }
        __syncthreads();

        // Phase 1: warps 2(m) x 4(n); warp tile 32 x 64
        {
            int wm = wid & 1, wn = wid >> 1;
            float acc[2][8][4];
#pragma unroll
            for (int mf = 0; mf < 2; mf++)
#pragma unroll
                for (int nf = 0; nf < 8; nf++)
#pragma unroll
                    for (int r = 0; r < 4; r++) acc[mf][nf][r] = 0.f;

#pragma unroll
            for (int k8 = 0; k8 < 8; k8++) {
                int kb = k8 * 8;
                uint32_t a[2][4];
#pragma unroll
                for (int mf = 0; mf < 2; mf++) {
                    int r = wm * 32 + mf * 16;
                    a[mf][0] = __float_as_uint(Xs[(r + gid    ) * X_ST + kb + tig    ]);
                    a[mf][1] = __float_as_uint(Xs[(r + gid + 8) * X_ST + kb + tig    ]);
                    a[mf][2] = __float_as_uint(Xs[(r + gid    ) * X_ST + kb + tig + 4]);
                    a[mf][3] = __float_as_uint(Xs[(r + gid + 8) * X_ST + kb + tig + 4]);
                }
#pragma unroll
                for (int nf = 0; nf < 8; nf++) {
                    int n = wn * 64 + nf * 8 + gid;
                    uint32_t b0 = __float_as_uint(Wg_t[n * WG_ST + kb + tig    ]);
                    uint32_t b1 = __float_as_uint(Wg_t[n * WG_ST + kb + tig + 4]);
                    mma8(acc[0][nf], a[0], b0, b1);
                    mma8(acc[1][nf], a[1], b0, b1);
                }
            }
            // sigmoid, gather O, store gated products
#pragma unroll
            for (int mf = 0; mf < 2; mf++) {
#pragma unroll
                for (int nf = 0; nf < 8; nf++) {
                    int mb  = wm * 32 + mf * 16 + gid;
                    int col = wn * 64 + nf * 8 + 2 * tig;
#pragma unroll
                    for (int r = 0; r < 4; r++) {
                        int m  = mb + ((r >= 2) ? 8 : 0);
                        int cl = col + (r & 1);
                        float gate = 1.0f / (1.0f + __expf(-acc[mf][nf][r]));
                        int hh = cl >> 5, cc2 = cl & 31;
                        float ov = g_O[((size_t)hh * NN + s * CC + cc2) * II + i0g + m];
                        gs[m * GS_ST + cl] = to_tf32(gate * ov);
                    }
                }
            }
        }
        __syncthreads();

        // Phase 2: warps 4(m) x 2(n); warp tile 16 x 32; K = 256
        {
            int wm2 = wid >> 1, wn2 = wid & 1;
            float acc2[4][4];
#pragma unroll
            for (int nf = 0; nf < 4; nf++)
#pragma unroll
                for (int r = 0; r < 4; r++) acc2[nf][r] = 0.f;

#pragma unroll 4
            for (int k8 = 0; k8 < 32; k8++) {
                int kb = k8 * 8;
                int r = wm2 * 16;
                uint32_t a[4];
                a[0] = __float_as_uint(gs[(r + gid    ) * GS_ST + kb + tig    ]);
                a[1] = __float_as_uint(gs[(r + gid + 8) * GS_ST + kb + tig    ]);
                a[2] = __float_as_uint(gs[(r + gid    ) * GS_ST + kb + tig + 4]);
                a[3] = __float_as_uint(gs[(r + gid + 8) * GS_ST + kb + tig + 4]);
#pragma unroll
                for (int nf = 0; nf < 4; nf++) {
                    int n = wn2 * 32 + nf * 8 + gid;
                    uint32_t b0 = __float_as_uint(Wo_t[n * WO_ST + kb + tig    ]);
                    uint32_t b1 = __float_as_uint(Wo_t[n * WO_ST + kb + tig + 4]);
                    mma8(acc2[nf], a, b0, b1);
                }
            }
#pragma unroll
            for (int nf = 0; nf < 4; nf++) {
                int m   = wm2 * 16 + gid;
                int col = wn2 * 32 + nf * 8 + 2 * tig;
                float2 v0 = make_float2(acc2[nf][0], acc2[nf][1]);
                float2 v1 = make_float2(acc2[nf][2], acc2[nf][3]);
                *(float2*)&out[(size_t)(row0 + m    ) * CM + col] = v0;
                *(float2*)&out[(size_t)(row0 + m + 8) * CM + col] = v1;
            }
        }
        __syncthreads();
    }
}

// ---------------------------------------------------------------------------
extern "C" void kernel_launch(void* const* d_in, const int* in_sizes, int n_in,
                              void* d_out, int out_size) {
    const float* msa  = (const float*)d_in[0];
    const float* pair = (const float*)d_in[1];
    const float* g1   = (const float*)d_in[2];
    const float* b1   = (const float*)d_in[3];
    const float* g2   = (const float*)d_in[4];
    const float* b2   = (const float*)d_in[5];
    const float* Wv   = (const float*)d_in[6];
    const float* Wb   = (const float*)d_in[7];
    const float* Wg   = (const float*)d_in[8];
    const float* Wo   = (const float*)d_in[9];
    float* out = (float*)d_out;

    cudaFuncSetAttribute(kAV, cudaFuncAttributeMaxDynamicSharedMemorySize, (int)AV_SMEM);
    cudaFuncSetAttribute(kD,  cudaFuncAttributeMaxDynamicSharedMemorySize, (int)KD_SMEM);
    cudaFuncSetAttribute(kE,  cudaFuncAttributeMaxDynamicSharedMemorySize, (int)E_SMEM);

    kA<<<SS * II / 16, 256>>>(msa, g1, b1);
    kB<<<II * II / 8, 256>>>(pair, g2, b2, Wb);
    kAV<<<SS * II / 128, 256, AV_SMEM>>>(Wv);
    kC<<<II * HH, 128>>>();
    kD<<<dim3(NN / 128, II / 128, HH), 128, KD_SMEM>>>();
    kE<<<E_GRID, 256, E_SMEM>>>(Wg, Wo, out);
}

// round 11
// speedup vs baseline: 2.7050x; 1.2862x over previous
#include <cuda_runtime.h>
#include <math.h>
#include <stdint.h>

#define SS 512
#define II 384
#define CM 64
#define CZ 128
#define HH 8
#define CC 32
#define HC 256
#define NN (SS*CC)      // 16384
#define EPS 1e-5f

// Scratch (static device allocations; allowed)
__device__ float g_N[SS * II * CM];            // msa_n (tf32)     [row = s*384+i][64]
__device__ float g_V[(size_t)HH * NN * II];    // V (tf32)         [h][n=s*32+c][j=i]
__device__ float g_W[II * HH * II];            // softmax weights  [i][h][j] (tf32)
__device__ float g_O[(size_t)HH * NN * II];    // einsum result    [row][hc = h*32+c]
__device__ float g_G[(size_t)SS * II * HC];    // sigmoid gate     [row][hc]

__device__ __forceinline__ float to_tf32(float x) {
    uint32_t u;
    asm("cvt.rna.tf32.f32 %0, %1;" : "=r"(u) : "f"(x));
    return __uint_as_float(u);
}

__device__ __forceinline__ void mma8(float* d, const uint32_t* a, uint32_t b0, uint32_t b1) {
    asm volatile(
        "mma.sync.aligned.m16n8k8.row.col.f32.tf32.tf32.f32 "
        "{%0,%1,%2,%3}, {%4,%5,%6,%7}, {%8,%9}, {%0,%1,%2,%3};"
        : "+f"(d[0]), "+f"(d[1]), "+f"(d[2]), "+f"(d[3])
        : "r"(a[0]), "r"(a[1]), "r"(a[2]), "r"(a[3]), "r"(b0), "r"(b1));
}

__device__ __forceinline__ uint32_t smem_u32(const void* p) {
    uint32_t a;
    asm("{ .reg .u64 t; cvta.to.shared.u64 t, %1; cvt.u32.u64 %0, t; }" : "=r"(a) : "l"(p));
    return a;
}
#define CP16(dst, src) \
    asm volatile("cp.async.ca.shared.global [%0], [%1], 16;" :: "r"(dst), "l"(src))

// ---------------------------------------------------------------------------
// K_A: LN(msa) -> g_N (tf32). 16 rows per block, 256 threads.
// ---------------------------------------------------------------------------
__global__ void kA(const float* __restrict__ msa, const float* __restrict__ gg,
                   const float* __restrict__ bb) {
    int t = threadIdx.x;
    int row0 = blockIdx.x * 16;
    int r = t >> 4, l = t & 15;
    const float* x = msa + (size_t)(row0 + r) * CM + l * 4;
    float v0 = x[0], v1 = x[1], v2 = x[2], v3 = x[3];
    float sum = v0 + v1 + v2 + v3;
    float sq  = v0*v0 + v1*v1 + v2*v2 + v3*v3;
#pragma unroll
    for (int o = 8; o > 0; o >>= 1) {
        sum += __shfl_xor_sync(0xffffffffu, sum, o);
        sq  += __shfl_xor_sync(0xffffffffu, sq,  o);
    }
    float mean = sum * (1.0f / CM);
    float var  = sq * (1.0f / CM) - mean * mean;
    float rstd = rsqrtf(var + EPS);
    int k0 = l * 4;
    float4 o4;
    o4.x = to_tf32((v0 - mean) * rstd * gg[k0+0] + bb[k0+0]);
    o4.y = to_tf32((v1 - mean) * rstd * gg[k0+1] + bb[k0+1]);
    o4.z = to_tf32((v2 - mean) * rstd * gg[k0+2] + bb[k0+2]);
    o4.w = to_tf32((v3 - mean) * rstd * gg[k0+3] + bb[k0+3]);
    *(float4*)(g_N + (size_t)(row0 + r) * CM + k0) = o4;
}

// ---------------------------------------------------------------------------
// K_B: LN(pair) @ W_bias -> g_W[i][h][j]. One warp per (i,j) row.
// ---------------------------------------------------------------------------
__global__ void kB(const float* __restrict__ pair, const float* __restrict__ gg,
                   const float* __restrict__ bb, const float* __restrict__ Wb) {
    int warp = threadIdx.x >> 5, lane = threadIdx.x & 31;
    int row = blockIdx.x * 8 + warp;  // i*384 + j
    const float4* x4 = (const float4*)(pair + (size_t)row * CZ);
    float4 v = x4[lane];
    float sum = v.x + v.y + v.z + v.w;
    float sq  = v.x*v.x + v.y*v.y + v.z*v.z + v.w*v.w;
#pragma unroll
    for (int o = 16; o > 0; o >>= 1) {
        sum += __shfl_xor_sync(0xffffffffu, sum, o);
        sq  += __shfl_xor_sync(0xffffffffu, sq,  o);
    }
    float mean = sum * (1.0f / CZ);
    float var  = sq * (1.0f / CZ) - mean * mean;
    float rstd = rsqrtf(var + EPS);
    int k0 = lane * 4;
    float n0 = (v.x - mean) * rstd * gg[k0+0] + bb[k0+0];
    float n1 = (v.y - mean) * rstd * gg[k0+1] + bb[k0+1];
    float n2 = (v.z - mean) * rstd * gg[k0+2] + bb[k0+2];
    float n3 = (v.w - mean) * rstd * gg[k0+3] + bb[k0+3];
    float ph[HH];
#pragma unroll
    for (int h = 0; h < HH; h++) {
        ph[h] = n0 * Wb[(k0+0)*HH + h] + n1 * Wb[(k0+1)*HH + h]
              + n2 * Wb[(k0+2)*HH + h] + n3 * Wb[(k0+3)*HH + h];
    }
#pragma unroll
    for (int h = 0; h < HH; h++) {
#pragma unroll
        for (int o = 16; o > 0; o >>= 1)
            ph[h] += __shfl_xor_sync(0xffffffffu, ph[h], o);
    }
    if (lane == 0) {
        int i = row / II, j = row % II;
#pragma unroll
        for (int h = 0; h < HH; h++)
            g_W[((size_t)i * HH + h) * II + j] = ph[h];
    }
}

// ---------------------------------------------------------------------------
// K_E1: G = sigmoid(g_N @ Wg) -> g_G[row][256] fp32. 512 threads, 16 warps
// (4m x 4n), warp tile 32x64. M-tile 128, K=64 single pass.
// ---------------------------------------------------------------------------
#define E1_ST_A 68
#define E1_ST_B 68
#define E1_OFF_B (128 * E1_ST_A)
#define E1_SMEM ((128 * E1_ST_A + 256 * E1_ST_B) * sizeof(float))  // 104448

__global__ void __launch_bounds__(512) kE1(const float* __restrict__ Wg) {
    extern __shared__ float sm[];
    float* As = sm;
    float* Bs = sm + E1_OFF_B;

    int t = threadIdx.x, lane = t & 31, wid = t >> 5;
    int gid = lane >> 2, tig = lane & 3;
    int wm = wid & 3, wn = wid >> 2;
    int row0 = blockIdx.x * 128;

    // A: 128x64 from g_N (already tf32)
#pragma unroll
    for (int q = 0; q < 4; q++) {
        int idx = t + 512 * q;
        int m = idx >> 4, k4 = (idx & 15) * 4;
        *(float4*)&As[m * E1_ST_A + k4] =
            *(const float4*)(g_N + (size_t)(row0 + m) * CM + k4);
    }
    // B: Wg [k=64][n=256] -> Bs[n][k], tf32
    {
        int n = t >> 1, kh = (t & 1) * 32;
#pragma unroll
        for (int k = 0; k < 32; k++)
            Bs[n * E1_ST_B + kh + k] = to_tf32(Wg[(size_t)(kh + k) * HC + n]);
    }
    __syncthreads();

    float acc[2][8][4];
#pragma unroll
    for (int mf = 0; mf < 2; mf++)
#pragma unroll
        for (int nf = 0; nf < 8; nf++)
#pragma unroll
            for (int r = 0; r < 4; r++) acc[mf][nf][r] = 0.f;

#pragma unroll
    for (int k8 = 0; k8 < 8; k8++) {
        int kb = k8 * 8;
        uint32_t a[2][4];
#pragma unroll
        for (int mf = 0; mf < 2; mf++) {
            int r = wm * 32 + mf * 16;
            a[mf][0] = __float_as_uint(As[(r + gid    ) * E1_ST_A + kb + tig    ]);
            a[mf][1] = __float_as_uint(As[(r + gid + 8) * E1_ST_A + kb + tig    ]);
            a[mf][2] = __float_as_uint(As[(r + gid    ) * E1_ST_A + kb + tig + 4]);
            a[mf][3] = __float_as_uint(As[(r + gid + 8) * E1_ST_A + kb + tig + 4]);
        }
#pragma unroll
        for (int nf = 0; nf < 8; nf++) {
            int n = wn * 64 + nf * 8 + gid;
            uint32_t b0 = __float_as_uint(Bs[n * E1_ST_B + kb + tig    ]);
            uint32_t b1 = __float_as_uint(Bs[n * E1_ST_B + kb + tig + 4]);
            mma8(acc[0][nf], a[0], b0, b1);
            mma8(acc[1][nf], a[1], b0, b1);
        }
    }

    // sigmoid + coalesced float2 stores
#pragma unroll
    for (int mf = 0; mf < 2; mf++) {
#pragma unroll
        for (int nf = 0; nf < 8; nf++) {
            int m   = wm * 32 + mf * 16 + gid;
            int col = wn * 64 + nf * 8 + 2 * tig;
            float2 v0, v1;
            v0.x = 1.0f / (1.0f + __expf(-acc[mf][nf][0]));
            v0.y = 1.0f / (1.0f + __expf(-acc[mf][nf][1]));
            v1.x = 1.0f / (1.0f + __expf(-acc[mf][nf][2]));
            v1.y = 1.0f / (1.0f + __expf(-acc[mf][nf][3]));
            *(float2*)&g_G[(size_t)(row0 + m    ) * HC + col] = v0;
            *(float2*)&g_G[(size_t)(row0 + m + 8) * HC + col] = v1;
        }
    }
}

// ---------------------------------------------------------------------------
// K_AV: V = g_N @ Wv via mma. M-tile 128, N=256, K=64.
// 256 threads, 8 warps (2m x 4n), warp tile 64x64.
// Epilogue writes g_V[h][s*32+c][i] (transposed, tf32) via smem staging.
// ---------------------------------------------------------------------------
#define AV_ST_A 68
#define AV_ST_B 68
#define AV_OFF_B (128 * AV_ST_A)
#define AV_SMEM ((128 * AV_ST_A + 256 * AV_ST_B) * sizeof(float))  // 104448
#define AV_CS 132

__global__ void __launch_bounds__(256) kAV(const float* __restrict__ Wv) {
    extern __shared__ float sm[];
    float* As = sm;
    float* Bs = sm + AV_OFF_B;
    float* Cs = sm;   // epilogue alias (64*132 = 8448 floats <= 8704)

    int t = threadIdx.x, lane = t & 31, wid = t >> 5;
    int gid = lane >> 2, tig = lane & 3;
    int wm = wid >> 2, wn = wid & 3;
    int row0 = blockIdx.x * 128;
    int s = row0 / II, i0 = row0 % II;

#pragma unroll
    for (int q = 0; q < 8; q++) {
        int idx = t + 256 * q;
        int m = idx >> 4, k4 = (idx & 15) * 4;
        *(float4*)&As[m * AV_ST_A + k4] =
            *(const float4*)(g_N + (size_t)(row0 + m) * CM + k4);
    }
    {
        int n = t;
#pragma unroll
        for (int k = 0; k < CM; k++)
            Bs[n * AV_ST_B + k] = to_tf32(Wv[(size_t)k * HC + n]);
    }
    __syncthreads();

    float acc[4][8][4];
#pragma unroll
    for (int mf = 0; mf < 4; mf++)
#pragma unroll
        for (int nf = 0; nf < 8; nf++)
#pragma unroll
            for (int r = 0; r < 4; r++) acc[mf][nf][r] = 0.f;

#pragma unroll
    for (int k8 = 0; k8 < 8; k8++) {
        int kb = k8 * 8;
        uint32_t a[4][4];
#pragma unroll
        for (int mf = 0; mf < 4; mf++) {
            int r = 64 * wm + mf * 16;
            a[mf][0] = __float_as_uint(As[(r + gid    ) * AV_ST_A + kb + tig    ]);
            a[mf][1] = __float_as_uint(As[(r + gid + 8) * AV_ST_A + kb + tig    ]);
            a[mf][2] = __float_as_uint(As[(r + gid    ) * AV_ST_A + kb + tig + 4]);
            a[mf][3] = __float_as_uint(As[(r + gid + 8) * AV_ST_A + kb + tig + 4]);
        }
#pragma unroll
        for (int nf = 0; nf < 8; nf++) {
            int n = 64 * wn + nf * 8 + gid;
            uint32_t b0 = __float_as_uint(Bs[n * AV_ST_B + kb + tig    ]);
            uint32_t b1 = __float_as_uint(Bs[n * AV_ST_B + kb + tig + 4]);
#pragma unroll
            for (int mf = 0; mf < 4; mf++) mma8(acc[mf][nf], a[mf], b0, b1);
        }
    }

    for (int qq = 0; qq < 4; qq++) {
        __syncthreads();
        if (wn == qq) {
#pragma unroll
            for (int mf = 0; mf < 4; mf++) {
#pragma unroll
                for (int nf = 0; nf < 8; nf++) {
                    int il = 64 * wm + mf * 16 + gid;
                    int nl = nf * 8 + 2 * tig;
                    Cs[ nl      * AV_CS + il    ] = to_tf32(acc[mf][nf][0]);
                    Cs[(nl + 1) * AV_CS + il    ] = to_tf32(acc[mf][nf][1]);
                    Cs[ nl      * AV_CS + il + 8] = to_tf32(acc[mf][nf][2]);
                    Cs[(nl + 1) * AV_CS + il + 8] = to_tf32(acc[mf][nf][3]);
                }
            }
        }
        __syncthreads();
        int c0 = t >> 2;            // 0..63 column within quarter
        int ic = (t & 3) * 32;      // i chunk
        int cl = qq * 64 + c0;
        int hh = cl >> 5, cc = cl & 31;
        float* dst = g_V + ((size_t)hh * NN + s * CC + cc) * II + i0 + ic;
#pragma unroll
        for (int q2 = 0; q2 < 8; q2++)
            *(float4*)&dst[q2 * 4] = *(const float4*)&Cs[c0 * AV_CS + ic + q2 * 4];
    }
}

// ---------------------------------------------------------------------------
// K_C: in-place softmax over j for each (i,h); output tf32-rounded.
// ---------------------------------------------------------------------------
__global__ void kC() {
    int row = blockIdx.x;  // i*8 + h
    float* p = g_W + (size_t)row * II;
    int t = threadIdx.x;
    __shared__ float red[128];
    float x0 = p[t], x1 = p[t + 128], x2 = p[t + 256];
    float m = fmaxf(x0, fmaxf(x1, x2));
    red[t] = m;
    __syncthreads();
    for (int o = 64; o > 0; o >>= 1) {
        if (t < o) red[t] = fmaxf(red[t], red[t + o]);
        __syncthreads();
    }
    m = red[0];
    __syncthreads();
    float e0 = __expf(x0 - m), e1 = __expf(x1 - m), e2 = __expf(x2 - m);
    red[t] = e0 + e1 + e2;
    __syncthreads();
    for (int o = 64; o > 0; o >>= 1) {
        if (t < o) red[t] += red[t + o];
        __syncthreads();
    }
    float inv = 1.0f / red[0];
    p[t]       = to_tf32(e0 * inv);
    p[t + 128] = to_tf32(e1 * inv);
    p[t + 256] = to_tf32(e2 * inv);
}

// ---------------------------------------------------------------------------
// K_D: tf32 mma GEMM per h, 2-stage cp.async, 128 threads, 4 warps (2x2),
// warp tile 64x64. Result written to g_O[row = s*II+i][h*32+c] (contiguous hc).
// ---------------------------------------------------------------------------
#define KD_PAD 36
#define KD_STG (128 * KD_PAD)
#define KD_CS_PAD 132
#define KD_SMEM (4 * KD_STG * sizeof(float))   // 73728 B

__global__ void __launch_bounds__(128, 2) kD() {
    extern __shared__ float sm[];
    float* Cs = sm;

    const int h  = blockIdx.z;
    const int i0 = blockIdx.y * 128;
    const int n0 = blockIdx.x * 128;
    int t = threadIdx.x, lane = t & 31, wid = t >> 5;
    int wm = wid >> 1, wn = wid & 1;
    int gid = lane >> 2, tig = lane & 3;
    uint32_t smb = smem_u32(sm);

    float acc[4][8][4];
#pragma unroll
    for (int mf = 0; mf < 4; mf++)
#pragma unroll
        for (int nf = 0; nf < 8; nf++)
#pragma unroll
            for (int r = 0; r < 4; r++) acc[mf][nf][r] = 0.f;

    auto prefetch = [&](int ch, int buf) {
        uint32_t a_base = smb + (uint32_t)(buf * 2 * KD_STG) * 4u;
        uint32_t b_base = a_base + (uint32_t)KD_STG * 4u;
        int j0 = ch * 32;
#pragma unroll
        for (int q = 0; q < 8; q++) {
            int f = t + 128 * q;
            int row = f >> 3, cv = (f & 7) * 4;
            CP16(a_base + (uint32_t)(row * KD_PAD + cv) * 4u,
                 g_W + ((size_t)(i0 + row) * HH + h) * II + j0 + cv);
            CP16(b_base + (uint32_t)(row * KD_PAD + cv) * 4u,
                 g_V + ((size_t)h * NN + n0 + row) * II + j0 + cv);
        }
        asm volatile("cp.async.commit_group;" ::: "memory");
    };

    prefetch(0, 0);

    for (int ch = 0; ch < 12; ch++) {
        if (ch < 11) {
            prefetch(ch + 1, (ch + 1) & 1);
            asm volatile("cp.async.wait_group 1;" ::: "memory");
        } else {
            asm volatile("cp.async.wait_group 0;" ::: "memory");
        }
        __syncthreads();
        const float* As = sm + (ch & 1) * 2 * KD_STG;
        const float* Bs = As + KD_STG;
#pragma unroll
        for (int k8 = 0; k8 < 4; k8++) {
            int kb = k8 * 8;
            uint32_t a[4][4];
#pragma unroll
            for (int mf = 0; mf < 4; mf++) {
                int r = 64 * wm + mf * 16;
                a[mf][0] = __float_as_uint(As[(r + gid    ) * KD_PAD + kb + tig    ]);
                a[mf][1] = __float_as_uint(As[(r + gid + 8) * KD_PAD + kb + tig    ]);
                a[mf][2] = __float_as_uint(As[(r + gid    ) * KD_PAD + kb + tig + 4]);
                a[mf][3] = __float_as_uint(As[(r + gid + 8) * KD_PAD + kb + tig + 4]);
            }
#pragma unroll
            for (int nf = 0; nf < 8; nf++) {
                int n = 64 * wn + nf * 8 + gid;
                uint32_t b0 = __float_as_uint(Bs[n * KD_PAD + kb + tig    ]);
                uint32_t b1 = __float_as_uint(Bs[n * KD_PAD + kb + tig + 4]);
#pragma unroll
                for (int mf = 0; mf < 4; mf++) mma8(acc[mf][nf], a[mf], b0, b1);
            }
        }
        __syncthreads();
    }

    // Epilogue: stage Cs[n_local][i_local], then write g_O[row][hc] with hc
    // contiguous per thread (128B per (s2,thread)).
    for (int half = 0; half < 2; half++) {
        __syncthreads();
        if (wn == half) {
#pragma unroll
            for (int mf = 0; mf < 4; mf++) {
#pragma unroll
                for (int nf = 0; nf < 8; nf++) {
                    int il = 64 * wm + mf * 16 + gid;
                    int nl = nf * 8 + 2 * tig;
                    Cs[ nl      * KD_CS_PAD + il    ] = acc[mf][nf][0];
                    Cs[(nl + 1) * KD_CS_PAD + il    ] = acc[mf][nf][1];
                    Cs[ nl      * KD_CS_PAD + il + 8] = acc[mf][nf][2];
                    Cs[(nl + 1) * KD_CS_PAD + il + 8] = acc[mf][nf][3];
                }
            }
        }
        __syncthreads();
        int sbase = (n0 + half * 64) >> 5;   // global s of first 32-col group
#pragma unroll
        for (int s2 = 0; s2 < 2; s2++) {
            float* dst = g_O + ((size_t)(sbase + s2) * II + i0 + t) * HC + h * CC;
#pragma unroll
            for (int c4 = 0; c4 < 8; c4++) {
                float4 v;
                v.x = Cs[(s2*32 + c4*4 + 0) * KD_CS_PAD + t];
                v.y = Cs[(s2*32 + c4*4 + 1) * KD_CS_PAD + t];
                v.z = Cs[(s2*32 + c4*4 + 2) * KD_CS_PAD + t];
                v.w = Cs[(s2*32 + c4*4 + 3) * KD_CS_PAD + t];
                *(float4*)(dst + c4 * 4) = v;
            }
        }
    }
}

// ---------------------------------------------------------------------------
// K_E2: out = tf32(g_G * g_O) @ Wo. M-tile 128, N=64, K=256 (4 chunks of 64).
// 256 threads, 8 warps (4m x 2n), warp tile 32x32. Wo kept whole in smem.
// ---------------------------------------------------------------------------
#define E2_ST_A 68
#define E2_ST_B 260
#define E2_OFF_B (128 * E2_ST_A)
#define E2_SMEM ((128 * E2_ST_A + 64 * E2_ST_B) * sizeof(float))  // 101376

__global__ void __launch_bounds__(256) kE2(const float* __restrict__ Wo,
                                           float* __restrict__ out) {
    extern __shared__ float sm[];
    float* As = sm;
    float* Bs = sm + E2_OFF_B;

    int t = threadIdx.x, lane = t & 31, wid = t >> 5;
    int gid = lane >> 2, tig = lane & 3;
    int wm = wid >> 1, wn = wid & 1;
    int row0 = blockIdx.x * 128;

    // B: Wo [k=256][n=64] -> Bs[n][k], tf32 (once)
    {
        int n = t >> 2, kq = (t & 3) * 64;
#pragma unroll
        for (int k = 0; k < 64; k++)
            Bs[n * E2_ST_B + kq + k] = to_tf32(Wo[(size_t)(kq + k) * CM + n]);
    }

    float acc[2][4][4];
#pragma unroll
    for (int mf = 0; mf < 2; mf++)
#pragma unroll
        for (int nf = 0; nf < 4; nf++)
#pragma unroll
            for (int r = 0; r < 4; r++) acc[mf][nf][r] = 0.f;

    for (int ch = 0; ch < 4; ch++) {
        int k0 = ch * 64;
        // A chunk: tf32(g_G * g_O), both [row][256] contiguous
#pragma unroll
        for (int q = 0; q < 8; q++) {
            int idx = t + 256 * q;
            int m = idx >> 4, k4 = (idx & 15) * 4;
            size_t base = (size_t)(row0 + m) * HC + k0 + k4;
            float4 gg4 = *(const float4*)(g_G + base);
            float4 oo4 = *(const float4*)(g_O + base);
            As[m * E2_ST_A + k4 + 0] = to_tf32(gg4.x * oo4.x);
            As[m * E2_ST_A + k4 + 1] = to_tf32(gg4.y * oo4.y);
            As[m * E2_ST_A + k4 + 2] = to_tf32(gg4.z * oo4.z);
            As[m * E2_ST_A + k4 + 3] = to_tf32(gg4.w * oo4.w);
        }
        __syncthreads();
#pragma unroll
        for (int k8 = 0; k8 < 8; k8++) {
            int kb = k8 * 8;
            uint32_t a[2][4];
#pragma unroll
            for (int mf = 0; mf < 2; mf++) {
                int r = wm * 32 + mf * 16;
                a[mf][0] = __float_as_uint(As[(r + gid    ) * E2_ST_A + kb + tig    ]);
                a[mf][1] = __float_as_uint(As[(r + gid + 8) * E2_ST_A + kb + tig    ]);
                a[mf][2] = __float_as_uint(As[(r + gid    ) * E2_ST_A + kb + tig + 4]);
                a[mf][3] = __float_as_uint(As[(r + gid + 8) * E2_ST_A + kb + tig + 4]);
            }
#pragma unroll
            for (int nf = 0; nf < 4; nf++) {
                int n = wn * 32 + nf * 8 + gid;
                uint32_t b0 = __float_as_uint(Bs[n * E2_ST_B + k0 + kb + tig    ]);
                uint32_t b1 = __float_as_uint(Bs[n * E2_ST_B + k0 + kb + tig + 4]);
                mma8(acc[0][nf], a[0], b0, b1);
                mma8(acc[1][nf], a[1], b0, b1);
            }
        }
        __syncthreads();
    }

#pragma unroll
    for (int mf = 0; mf < 2; mf++) {
#pragma unroll
        for (int nf = 0; nf < 4; nf++) {
            int m   = wm * 32 + mf * 16 + gid;
            int col = wn * 32 + nf * 8 + 2 * tig;
            float2 v0 = make_float2(acc[mf][nf][0], acc[mf][nf][1]);
            float2 v1 = make_float2(acc[mf][nf][2], acc[mf][nf][3]);
            *(float2*)&out[(size_t)(row0 + m    ) * CM + col] = v0;
            *(float2*)&out[(size_t)(row0 + m + 8) * CM + col] = v1;
        }
    }
}

// ---------------------------------------------------------------------------
extern "C" void kernel_launch(void* const* d_in, const int* in_sizes, int n_in,
                              void* d_out, int out_size) {
    const float* msa  = (const float*)d_in[0];
    const float* pair = (const float*)d_in[1];
    const float* g1   = (const float*)d_in[2];
    const float* b1   = (const float*)d_in[3];
    const float* g2   = (const float*)d_in[4];
    const float* b2   = (const float*)d_in[5];
    const float* Wv   = (const float*)d_in[6];
    const float* Wb   = (const float*)d_in[7];
    const float* Wg   = (const float*)d_in[8];
    const float* Wo   = (const float*)d_in[9];
    float* out = (float*)d_out;

    cudaFuncSetAttribute(kE1, cudaFuncAttributeMaxDynamicSharedMemorySize, (int)E1_SMEM);
    cudaFuncSetAttribute(kAV, cudaFuncAttributeMaxDynamicSharedMemorySize, (int)AV_SMEM);
    cudaFuncSetAttribute(kD,  cudaFuncAttributeMaxDynamicSharedMemorySize, (int)KD_SMEM);
    cudaFuncSetAttribute(kE2, cudaFuncAttributeMaxDynamicSharedMemorySize, (int)E2_SMEM);

    // Order chosen so launch index 3 (the ncu capture slot) = kAV.
    kA<<<SS * II / 16, 256>>>(msa, g1, b1);
    kB<<<II * II / 8, 256>>>(pair, g2, b2, Wb);
    kE1<<<SS * II / 128, 512, E1_SMEM>>>(Wg);
    kAV<<<SS * II / 128, 256, AV_SMEM>>>(Wv);
    kC<<<II * HH, 128>>>();
    kD<<<dim3(NN / 128, II / 128, HH), 128, KD_SMEM>>>();
    kE2<<<SS * II / 128, 256, E2_SMEM>>>(Wo, out);
}

// round 16
// speedup vs baseline: 2.8277x; 1.0454x over previous
#include <cuda_runtime.h>
#include <math.h>
#include <stdint.h>

#define SS 512
#define II 384
#define CM 64
#define CZ 128
#define HH 8
#define CC 32
#define HC 256
#define NN (SS*CC)      // 16384
#define EPS 1e-5f

// Scratch (static device allocations; allowed)
__device__ float g_N[SS * II * CM];            // msa_n (tf32)     [row = s*384+i][64]
__device__ float g_V[(size_t)HH * NN * II];    // V (tf32)         [h][n=s*32+c][j=i]
__device__ float g_W[II * HH * II];            // softmax weights  [i][h][j] (tf32)
__device__ float g_O[(size_t)HH * NN * II];    // gated einsum     [row][hc = h*32+c]
__device__ float g_G[(size_t)SS * II * HC];    // sigmoid gate     [row][hc]

__device__ __forceinline__ float to_tf32(float x) {
    uint32_t u;
    asm("cvt.rna.tf32.f32 %0, %1;" : "=r"(u) : "f"(x));
    return __uint_as_float(u);
}

__device__ __forceinline__ void mma8(float* d, const uint32_t* a, uint32_t b0, uint32_t b1) {
    asm volatile(
        "mma.sync.aligned.m16n8k8.row.col.f32.tf32.tf32.f32 "
        "{%0,%1,%2,%3}, {%4,%5,%6,%7}, {%8,%9}, {%0,%1,%2,%3};"
        : "+f"(d[0]), "+f"(d[1]), "+f"(d[2]), "+f"(d[3])
        : "r"(a[0]), "r"(a[1]), "r"(a[2]), "r"(a[3]), "r"(b0), "r"(b1));
}

__device__ __forceinline__ uint32_t smem_u32(const void* p) {
    uint32_t a;
    asm("{ .reg .u64 t; cvta.to.shared.u64 t, %1; cvt.u32.u64 %0, t; }" : "=r"(a) : "l"(p));
    return a;
}
#define CP16(dst, src) \
    asm volatile("cp.async.ca.shared.global [%0], [%1], 16;" :: "r"(dst), "l"(src))

// ---------------------------------------------------------------------------
// K_A: LN(msa) -> g_N (tf32). 16 rows per block, 256 threads.
// ---------------------------------------------------------------------------
__global__ void kA(const float* __restrict__ msa, const float* __restrict__ gg,
                   const float* __restrict__ bb) {
    int t = threadIdx.x;
    int row0 = blockIdx.x * 16;
    int r = t >> 4, l = t & 15;
    const float* x = msa + (size_t)(row0 + r) * CM + l * 4;
    float v0 = x[0], v1 = x[1], v2 = x[2], v3 = x[3];
    float sum = v0 + v1 + v2 + v3;
    float sq  = v0*v0 + v1*v1 + v2*v2 + v3*v3;
#pragma unroll
    for (int o = 8; o > 0; o >>= 1) {
        sum += __shfl_xor_sync(0xffffffffu, sum, o);
        sq  += __shfl_xor_sync(0xffffffffu, sq,  o);
    }
    float mean = sum * (1.0f / CM);
    float var  = sq * (1.0f / CM) - mean * mean;
    float rstd = rsqrtf(var + EPS);
    int k0 = l * 4;
    float4 o4;
    o4.x = to_tf32((v0 - mean) * rstd * gg[k0+0] + bb[k0+0]);
    o4.y = to_tf32((v1 - mean) * rstd * gg[k0+1] + bb[k0+1]);
    o4.z = to_tf32((v2 - mean) * rstd * gg[k0+2] + bb[k0+2]);
    o4.w = to_tf32((v3 - mean) * rstd * gg[k0+3] + bb[k0+3]);
    *(float4*)(g_N + (size_t)(row0 + r) * CM + k0) = o4;
}

// ---------------------------------------------------------------------------
// K_B: LN(pair) @ W_bias -> g_W[i][h][j]. One warp per (i,j) row.  (proven)
// ---------------------------------------------------------------------------
__global__ void kB(const float* __restrict__ pair, const float* __restrict__ gg,
                   const float* __restrict__ bb, const float* __restrict__ Wb) {
    int warp = threadIdx.x >> 5, lane = threadIdx.x & 31;
    int row = blockIdx.x * 8 + warp;  // i*384 + j
    const float4* x4 = (const float4*)(pair + (size_t)row * CZ);
    float4 v = x4[lane];
    float sum = v.x + v.y + v.z + v.w;
    float sq  = v.x*v.x + v.y*v.y + v.z*v.z + v.w*v.w;
#pragma unroll
    for (int o = 16; o > 0; o >>= 1) {
        sum += __shfl_xor_sync(0xffffffffu, sum, o);
        sq  += __shfl_xor_sync(0xffffffffu, sq,  o);
    }
    float mean = sum * (1.0f / CZ);
    float var  = sq * (1.0f / CZ) - mean * mean;
    float rstd = rsqrtf(var + EPS);
    int k0 = lane * 4;
    float n0 = (v.x - mean) * rstd * gg[k0+0] + bb[k0+0];
    float n1 = (v.y - mean) * rstd * gg[k0+1] + bb[k0+1];
    float n2 = (v.z - mean) * rstd * gg[k0+2] + bb[k0+2];
    float n3 = (v.w - mean) * rstd * gg[k0+3] + bb[k0+3];
    float ph[HH];
#pragma unroll
    for (int h = 0; h < HH; h++) {
        ph[h] = n0 * Wb[(k0+0)*HH + h] + n1 * Wb[(k0+1)*HH + h]
              + n2 * Wb[(k0+2)*HH + h] + n3 * Wb[(k0+3)*HH + h];
    }
#pragma unroll
    for (int h = 0; h < HH; h++) {
#pragma unroll
        for (int o = 16; o > 0; o >>= 1)
            ph[h] += __shfl_xor_sync(0xffffffffu, ph[h], o);
    }
    if (lane == 0) {
        int i = row / II, j = row % II;
#pragma unroll
        for (int h = 0; h < HH; h++)
            g_W[((size_t)i * HH + h) * II + j] = ph[h];
    }
}

// ---------------------------------------------------------------------------
// K_C: in-place softmax over j for each (i,h); output tf32-rounded. (proven)
// ---------------------------------------------------------------------------
__global__ void kC() {
    int row = blockIdx.x;  // i*8 + h
    float* p = g_W + (size_t)row * II;
    int t = threadIdx.x;
    __shared__ float red[128];
    float x0 = p[t], x1 = p[t + 128], x2 = p[t + 256];
    float m = fmaxf(x0, fmaxf(x1, x2));
    red[t] = m;
    __syncthreads();
    for (int o = 64; o > 0; o >>= 1) {
        if (t < o) red[t] = fmaxf(red[t], red[t + o]);
        __syncthreads();
    }
    m = red[0];
    __syncthreads();
    float e0 = __expf(x0 - m), e1 = __expf(x1 - m), e2 = __expf(x2 - m);
    red[t] = e0 + e1 + e2;
    __syncthreads();
    for (int o = 64; o > 0; o >>= 1) {
        if (t < o) red[t] += red[t + o];
        __syncthreads();
    }
    float inv = 1.0f / red[0];
    p[t]       = to_tf32(e0 * inv);
    p[t + 128] = to_tf32(e1 * inv);
    p[t + 256] = to_tf32(e2 * inv);
}

// ---------------------------------------------------------------------------
// K_AV: V = g_N @ Wv via mma. M-tile 128, N=256, K=64. 512 threads, 16 warps
// (4m x 4n), warp tile 32x64 (occupancy fix vs 256-thread version).
// Epilogue writes g_V[h][s*32+c][i] (transposed, tf32) via smem staging.
// ---------------------------------------------------------------------------
#define AV_ST_A 68
#define AV_ST_B 68
#define AV_OFF_B (128 * AV_ST_A)
#define AV_SMEM ((128 * AV_ST_A + 256 * AV_ST_B) * sizeof(float))  // 104448
#define AV_CS 132

__global__ void __launch_bounds__(512) kAV(const float* __restrict__ Wv) {
    extern __shared__ float sm[];
    float* As = sm;
    float* Bs = sm + AV_OFF_B;
    float* Cs = sm;   // epilogue alias (64*132 = 8448 floats <= 8704)

    int t = threadIdx.x, lane = t & 31, wid = t >> 5;
    int gid = lane >> 2, tig = lane & 3;
    int wm = wid & 3, wn = wid >> 2;
    int row0 = blockIdx.x * 128;
    int s = row0 / II, i0 = row0 % II;

#pragma unroll
    for (int q = 0; q < 4; q++) {
        int idx = t + 512 * q;
        int m = idx >> 4, k4 = (idx & 15) * 4;
        *(float4*)&As[m * AV_ST_A + k4] =
            *(const float4*)(g_N + (size_t)(row0 + m) * CM + k4);
    }
    {
        int n = t >> 1, kh = (t & 1) * 32;
#pragma unroll
        for (int k = 0; k < 32; k++)
            Bs[n * AV_ST_B + kh + k] = to_tf32(Wv[(size_t)(kh + k) * HC + n]);
    }
    __syncthreads();

    float acc[2][8][4];
#pragma unroll
    for (int mf = 0; mf < 2; mf++)
#pragma unroll
        for (int nf = 0; nf < 8; nf++)
#pragma unroll
            for (int r = 0; r < 4; r++) acc[mf][nf][r] = 0.f;

#pragma unroll
    for (int k8 = 0; k8 < 8; k8++) {
        int kb = k8 * 8;
        uint32_t a[2][4];
#pragma unroll
        for (int mf = 0; mf < 2; mf++) {
            int r = wm * 32 + mf * 16;
            a[mf][0] = __float_as_uint(As[(r + gid    ) * AV_ST_A + kb + tig    ]);
            a[mf][1] = __float_as_uint(As[(r + gid + 8) * AV_ST_A + kb + tig    ]);
            a[mf][2] = __float_as_uint(As[(r + gid    ) * AV_ST_A + kb + tig + 4]);
            a[mf][3] = __float_as_uint(As[(r + gid + 8) * AV_ST_A + kb + tig + 4]);
        }
#pragma unroll
        for (int nf = 0; nf < 8; nf++) {
            int n = wn * 64 + nf * 8 + gid;
            uint32_t b0 = __float_as_uint(Bs[n * AV_ST_B + kb + tig    ]);
            uint32_t b1 = __float_as_uint(Bs[n * AV_ST_B + kb + tig + 4]);
            mma8(acc[0][nf], a[0], b0, b1);
            mma8(acc[1][nf], a[1], b0, b1);
        }
    }

    // 4 quarters of 64 columns; warps with wn==qq stage, all 512 threads write.
    for (int qq = 0; qq < 4; qq++) {
        __syncthreads();
        if (wn == qq) {
#pragma unroll
            for (int mf = 0; mf < 2; mf++) {
#pragma unroll
                for (int nf = 0; nf < 8; nf++) {
                    int il = wm * 32 + mf * 16 + gid;
                    int nl = nf * 8 + 2 * tig;
                    Cs[ nl      * AV_CS + il    ] = to_tf32(acc[mf][nf][0]);
                    Cs[(nl + 1) * AV_CS + il    ] = to_tf32(acc[mf][nf][1]);
                    Cs[ nl      * AV_CS + il + 8] = to_tf32(acc[mf][nf][2]);
                    Cs[(nl + 1) * AV_CS + il + 8] = to_tf32(acc[mf][nf][3]);
                }
            }
        }
        __syncthreads();
        int c0 = t >> 3;            // 0..63 column within quarter
        int ic = (t & 7) * 16;      // i chunk
        int cl = qq * 64 + c0;
        int hh = cl >> 5, cc = cl & 31;
        float* dst = g_V + ((size_t)hh * NN + s * CC + cc) * II + i0 + ic;
#pragma unroll
        for (int q2 = 0; q2 < 4; q2++)
            *(float4*)&dst[q2 * 4] = *(const float4*)&Cs[c0 * AV_CS + ic + q2 * 4];
    }
}

// ---------------------------------------------------------------------------
// K_E1: G = sigmoid(g_N @ Wg) -> g_G[row][256] fp32. 512 threads, 16 warps
// (4m x 4n), warp tile 32x64. M-tile 128, K=64 single pass.
// ---------------------------------------------------------------------------
#define E1_ST_A 68
#define E1_ST_B 68
#define E1_OFF_B (128 * E1_ST_A)
#define E1_SMEM ((128 * E1_ST_A + 256 * E1_ST_B) * sizeof(float))  // 104448

__global__ void __launch_bounds__(512) kE1(const float* __restrict__ Wg) {
    extern __shared__ float sm[];
    float* As = sm;
    float* Bs = sm + E1_OFF_B;

    int t = threadIdx.x, lane = t & 31, wid = t >> 5;
    int gid = lane >> 2, tig = lane & 3;
    int wm = wid & 3, wn = wid >> 2;
    int row0 = blockIdx.x * 128;

#pragma unroll
    for (int q = 0; q < 4; q++) {
        int idx = t + 512 * q;
        int m = idx >> 4, k4 = (idx & 15) * 4;
        *(float4*)&As[m * E1_ST_A + k4] =
            *(const float4*)(g_N + (size_t)(row0 + m) * CM + k4);
    }
    {
        int n = t >> 1, kh = (t & 1) * 32;
#pragma unroll
        for (int k = 0; k < 32; k++)
            Bs[n * E1_ST_B + kh + k] = to_tf32(Wg[(size_t)(kh + k) * HC + n]);
    }
    __syncthreads();

    float acc[2][8][4];
#pragma unroll
    for (int mf = 0; mf < 2; mf++)
#pragma unroll
        for (int nf = 0; nf < 8; nf++)
#pragma unroll
            for (int r = 0; r < 4; r++) acc[mf][nf][r] = 0.f;

#pragma unroll
    for (int k8 = 0; k8 < 8; k8++) {
        int kb = k8 * 8;
        uint32_t a[2][4];
#pragma unroll
        for (int mf = 0; mf < 2; mf++) {
            int r = wm * 32 + mf * 16;
            a[mf][0] = __float_as_uint(As[(r + gid    ) * E1_ST_A + kb + tig    ]);
            a[mf][1] = __float_as_uint(As[(r + gid + 8) * E1_ST_A + kb + tig    ]);
            a[mf][2] = __float_as_uint(As[(r + gid    ) * E1_ST_A + kb + tig + 4]);
            a[mf][3] = __float_as_uint(As[(r + gid + 8) * E1_ST_A + kb + tig + 4]);
        }
#pragma unroll
        for (int nf = 0; nf < 8; nf++) {
            int n = wn * 64 + nf * 8 + gid;
            uint32_t b0 = __float_as_uint(Bs[n * E1_ST_B + kb + tig    ]);
            uint32_t b1 = __float_as_uint(Bs[n * E1_ST_B + kb + tig + 4]);
            mma8(acc[0][nf], a[0], b0, b1);
            mma8(acc[1][nf], a[1], b0, b1);
        }
    }

#pragma unroll
    for (int mf = 0; mf < 2; mf++) {
#pragma unroll
        for (int nf = 0; nf < 8; nf++) {
            int m   = wm * 32 + mf * 16 + gid;
            int col = wn * 64 + nf * 8 + 2 * tig;
            float2 v0, v1;
            v0.x = 1.0f / (1.0f + __expf(-acc[mf][nf][0]));
            v0.y = 1.0f / (1.0f + __expf(-acc[mf][nf][1]));
            v1.x = 1.0f / (1.0f + __expf(-acc[mf][nf][2]));
            v1.y = 1.0f / (1.0f + __expf(-acc[mf][nf][3]));
            *(float2*)&g_G[(size_t)(row0 + m    ) * HC + col] = v0;
            *(float2*)&g_G[(size_t)(row0 + m + 8) * HC + col] = v1;
        }
    }
}

// ---------------------------------------------------------------------------
// K_D: tf32 mma GEMM per h, 2-stage cp.async, 128 threads, 4 warps (2x2),
// warp tile 64x64. Epilogue applies sigmoid gate from g_G and writes
// g_O[row = s*II+i][h*32+c] = tf32(gate * val).
// ---------------------------------------------------------------------------
#define KD_PAD 36
#define KD_STG (128 * KD_PAD)
#define KD_CS_PAD 132
#define KD_SMEM (4 * KD_STG * sizeof(float))   // 73728 B

__global__ void __launch_bounds__(128, 2) kD() {
    extern __shared__ float sm[];
    float* Cs = sm;

    const int h  = blockIdx.z;
    const int i0 = blockIdx.y * 128;
    const int n0 = blockIdx.x * 128;
    int t = threadIdx.x, lane = t & 31, wid = t >> 5;
    int wm = wid >> 1, wn = wid & 1;
    int gid = lane >> 2, tig = lane & 3;
    uint32_t smb = smem_u32(sm);

    float acc[4][8][4];
#pragma unroll
    for (int mf = 0; mf < 4; mf++)
#pragma unroll
        for (int nf = 0; nf < 8; nf++)
#pragma unroll
            for (int r = 0; r < 4; r++) acc[mf][nf][r] = 0.f;

    auto prefetch = [&](int ch, int buf) {
        uint32_t a_base = smb + (uint32_t)(buf * 2 * KD_STG) * 4u;
        uint32_t b_base = a_base + (uint32_t)KD_STG * 4u;
        int j0 = ch * 32;
#pragma unroll
        for (int q = 0; q < 8; q++) {
            int f = t + 128 * q;
            int row = f >> 3, cv = (f & 7) * 4;
            CP16(a_base + (uint32_t)(row * KD_PAD + cv) * 4u,
                 g_W + ((size_t)(i0 + row) * HH + h) * II + j0 + cv);
            CP16(b_base + (uint32_t)(row * KD_PAD + cv) * 4u,
                 g_V + ((size_t)h * NN + n0 + row) * II + j0 + cv);
        }
        asm volatile("cp.async.commit_group;" ::: "memory");
    };

    prefetch(0, 0);

    for (int ch = 0; ch < 12; ch++) {
        if (ch < 11) {
            prefetch(ch + 1, (ch + 1) & 1);
            asm volatile("cp.async.wait_group 1;" ::: "memory");
        } else {
            asm volatile("cp.async.wait_group 0;" ::: "memory");
        }
        __syncthreads();
        const float* As = sm + (ch & 1) * 2 * KD_STG;
        const float* Bs = As + KD_STG;
#pragma unroll
        for (int k8 = 0; k8 < 4; k8++) {
            int kb = k8 * 8;
            uint32_t a[4][4];
#pragma unroll
            for (int mf = 0; mf < 4; mf++) {
                int r = 64 * wm + mf * 16;
                a[mf][0] = __float_as_uint(As[(r + gid    ) * KD_PAD + kb + tig    ]);
                a[mf][1] = __float_as_uint(As[(r + gid + 8) * KD_PAD + kb + tig    ]);
                a[mf][2] = __float_as_uint(As[(r + gid    ) * KD_PAD + kb + tig + 4]);
                a[mf][3] = __float_as_uint(As[(r + gid + 8) * KD_PAD + kb + tig + 4]);
            }
#pragma unroll
            for (int nf = 0; nf < 8; nf++) {
                int n = 64 * wn + nf * 8 + gid;
                uint32_t b0 = __float_as_uint(Bs[n * KD_PAD + kb + tig    ]);
                uint32_t b1 = __float_as_uint(Bs[n * KD_PAD + kb + tig + 4]);
#pragma unroll
                for (int mf = 0; mf < 4; mf++) mma8(acc[mf][nf], a[mf], b0, b1);
            }
        }
        __syncthreads();
    }

    // Epilogue: stage Cs[n_local][i_local]; apply gate; write g_O[row][hc].
    for (int half = 0; half < 2; half++) {
        __syncthreads();
        if (wn == half) {
#pragma unroll
            for (int mf = 0; mf < 4; mf++) {
#pragma unroll
                for (int nf = 0; nf < 8; nf++) {
                    int il = 64 * wm + mf * 16 + gid;
                    int nl = nf * 8 + 2 * tig;
                    Cs[ nl      * KD_CS_PAD + il    ] = acc[mf][nf][0];
                    Cs[(nl + 1) * KD_CS_PAD + il    ] = acc[mf][nf][1];
                    Cs[ nl      * KD_CS_PAD + il + 8] = acc[mf][nf][2];
                    Cs[(nl + 1) * KD_CS_PAD + il + 8] = acc[mf][nf][3];
                }
            }
        }
        __syncthreads();
        int sbase = (n0 + half * 64) >> 5;   // global s of first 32-col group
#pragma unroll
        for (int s2 = 0; s2 < 2; s2++) {
            size_t off = ((size_t)(sbase + s2) * II + i0 + t) * HC + h * CC;
            float* dst = g_O + off;
            const float* gsrc = g_G + off;
#pragma unroll
            for (int c4 = 0; c4 < 8; c4++) {
                float4 g4 = *(const float4*)(gsrc + c4 * 4);
                float4 v;
                v.x = to_tf32(Cs[(s2*32 + c4*4 + 0) * KD_CS_PAD + t] * g4.x);
                v.y = to_tf32(Cs[(s2*32 + c4*4 + 1) * KD_CS_PAD + t] * g4.y);
                v.z = to_tf32(Cs[(s2*32 + c4*4 + 2) * KD_CS_PAD + t] * g4.z);
                v.w = to_tf32(Cs[(s2*32 + c4*4 + 3) * KD_CS_PAD + t] * g4.w);
                *(float4*)(dst + c4 * 4) = v;
            }
        }
    }
}

// ---------------------------------------------------------------------------
// K_E2: out = g_O @ Wo (g_O already gated+tf32). M-tile 128, N=64, K=256
// (4 chunks of 64, register-prefetch pipeline). 256 threads, 8 warps
// (4m x 2n), warp tile 32x32. Wo kept whole in smem.
// ---------------------------------------------------------------------------
#define E2_ST_A 68
#define E2_ST_B 260
#define E2_OFF_B (128 * E2_ST_A)
#define E2_SMEM ((128 * E2_ST_A + 64 * E2_ST_B) * sizeof(float))  // 101376

__global__ void __launch_bounds__(256) kE2(const float* __restrict__ Wo,
                                           float* __restrict__ out) {
    extern __shared__ float sm[];
    float* As = sm;
    float* Bs = sm + E2_OFF_B;

    int t = threadIdx.x, lane = t & 31, wid = t >> 5;
    int gid = lane >> 2, tig = lane & 3;
    int wm = wid >> 1, wn = wid & 1;
    int row0 = blockIdx.x * 128;

    // B: Wo [k=256][n=64] -> Bs[n][k], tf32 (once)
    {
        int n = t >> 2, kq = (t & 3) * 64;
#pragma unroll
        for (int k = 0; k < 64; k++)
            Bs[n * E2_ST_B + kq + k] = to_tf32(Wo[(size_t)(kq + k) * CM + n]);
    }

    float acc[2][4][4];
#pragma unroll
    for (int mf = 0; mf < 2; mf++)
#pragma unroll
        for (int nf = 0; nf < 4; nf++)
#pragma unroll
            for (int r = 0; r < 4; r++) acc[mf][nf][r] = 0.f;

    float4 pf[8];
    // prefetch chunk 0
#pragma unroll
    for (int q = 0; q < 8; q++) {
        int idx = t + 256 * q;
        int m = idx >> 4, k4 = (idx & 15) * 4;
        pf[q] = *(const float4*)(g_O + (size_t)(row0 + m) * HC + k4);
    }

    for (int ch = 0; ch < 4; ch++) {
        int k0 = ch * 64;
        // store current chunk to smem
#pragma unroll
        for (int q = 0; q < 8; q++) {
            int idx = t + 256 * q;
            int m = idx >> 4, k4 = (idx & 15) * 4;
            *(float4*)&As[m * E2_ST_A + k4] = pf[q];
        }
        __syncthreads();
        // issue loads for next chunk (overlap with mma below)
        if (ch < 3) {
#pragma unroll
            for (int q = 0; q < 8; q++) {
                int idx = t + 256 * q;
                int m = idx >> 4, k4 = (idx & 15) * 4;
                pf[q] = *(const float4*)(g_O + (size_t)(row0 + m) * HC + k0 + 64 + k4);
            }
        }
#pragma unroll
        for (int k8 = 0; k8 < 8; k8++) {
            int kb = k8 * 8;
            uint32_t a[2][4];
#pragma unroll
            for (int mf = 0; mf < 2; mf++) {
                int r = wm * 32 + mf * 16;
                a[mf][0] = __float_as_uint(As[(r + gid    ) * E2_ST_A + kb + tig    ]);
                a[mf][1] = __float_as_uint(As[(r + gid + 8) * E2_ST_A + kb + tig    ]);
                a[mf][2] = __float_as_uint(As[(r + gid    ) * E2_ST_A + kb + tig + 4]);
                a[mf][3] = __float_as_uint(As[(r + gid + 8) * E2_ST_A + kb + tig + 4]);
            }
#pragma unroll
            for (int nf = 0; nf < 4; nf++) {
                int n = wn * 32 + nf * 8 + gid;
                uint32_t b0 = __float_as_uint(Bs[n * E2_ST_B + k0 + kb + tig    ]);
                uint32_t b1 = __float_as_uint(Bs[n * E2_ST_B + k0 + kb + tig + 4]);
                mma8(acc[0][nf], a[0], b0, b1);
                mma8(acc[1][nf], a[1], b0, b1);
            }
        }
        __syncthreads();
    }

#pragma unroll
    for (int mf = 0; mf < 2; mf++) {
#pragma unroll
        for (int nf = 0; nf < 4; nf++) {
            int m   = wm * 32 + mf * 16 + gid;
            int col = wn * 32 + nf * 8 + 2 * tig;
            float2 v0 = make_float2(acc[mf][nf][0], acc[mf][nf][1]);
            float2 v1 = make_float2(acc[mf][nf][2], acc[mf][nf][3]);
            *(float2*)&out[(size_t)(row0 + m    ) * CM + col] = v0;
            *(float2*)&out[(size_t)(row0 + m + 8) * CM + col] = v1;
        }
    }
}

// ---------------------------------------------------------------------------
extern "C" void kernel_launch(void* const* d_in, const int* in_sizes, int n_in,
                              void* d_out, int out_size) {
    const float* msa  = (const float*)d_in[0];
    const float* pair = (const float*)d_in[1];
    const float* g1   = (const float*)d_in[2];
    const float* b1   = (const float*)d_in[3];
    const float* g2   = (const float*)d_in[4];
    const float* b2   = (const float*)d_in[5];
    const float* Wv   = (const float*)d_in[6];
    const float* Wb   = (const float*)d_in[7];
    const float* Wg   = (const float*)d_in[8];
    const float* Wo   = (const float*)d_in[9];
    float* out = (float*)d_out;

    cudaFuncSetAttribute(kAV, cudaFuncAttributeMaxDynamicSharedMemorySize, (int)AV_SMEM);
    cudaFuncSetAttribute(kE1, cudaFuncAttributeMaxDynamicSharedMemorySize, (int)E1_SMEM);
    cudaFuncSetAttribute(kD,  cudaFuncAttributeMaxDynamicSharedMemorySize, (int)KD_SMEM);
    cudaFuncSetAttribute(kE2, cudaFuncAttributeMaxDynamicSharedMemorySize, (int)E2_SMEM);

    // Launch index 3 (ncu capture slot) = kAV (512-thread version).
    kA<<<SS * II / 16, 256>>>(msa, g1, b1);
    kB<<<II * II / 8, 256>>>(pair, g2, b2, Wb);
    kC<<<II * HH, 128>>>();
    kAV<<<SS * II / 128, 512, AV_SMEM>>>(Wv);
    kE1<<<SS * II / 128, 512, E1_SMEM>>>(Wg);
    kD<<<dim3(NN / 128, II / 128, HH), 128, KD_SMEM>>>();
    kE2<<<SS * II / 128, 256, E2_SMEM>>>(Wo, out);
}